// round 1
// baseline (speedup 1.0000x reference)
#include <cuda_runtime.h>
#include <cuda_bf16.h>

#define Nn 100000
#define Ee 2400000
#define Dd 256

// ---------------- device scratch (static, no allocation) ----------------
__device__ __align__(16) float d_tmp1[Nn * 64];   // x@W1+b1
__device__ __align__(16) float d_tmp2[Nn * 32];   // e1@W2+b2
__device__ __align__(16) float d_h1[Nn * 32];     // emb@Wg1
__device__ __align__(16) float d_aggP[Nn * 32];   // conv1 accum (ppmi)
__device__ __align__(16) float d_aggA[Nn * 32];   // conv1 accum (gcn)
__device__ __align__(16) float d_fp[Nn * 32];     // relu(aggP)
__device__ __align__(16) float d_fa[Nn * 32];     // relu(aggA)
__device__ __align__(16) float d_hcatP[Nn * 64];  // fp@[Wg2|Wg3]
__device__ __align__(16) float d_hcatA[Nn * 64];  // fa@[Wg2|Wg3]
__device__ __align__(16) float d_acc2P[Nn * 64];  // [mu_p | logvar_p] accum
__device__ __align__(16) float d_acc2A[Nn * 64];  // [mu_a | logvar_a] accum
__device__ float d_degP[Nn];                      // deg -> dinv (ppmi)
__device__ float d_degG[Nn];                      // deg -> dinv (gcn)
__device__ float d_sum1[64], d_ssq1[64];
__device__ float d_sum2[32], d_ssq2[32];
__device__ float d_mean1[64], d_rstd1[64];
__device__ float d_mean2[32], d_rstd2[32];

__device__ __forceinline__ float elu_f(float x) { return x > 0.f ? x : expm1f(x); }

__device__ __forceinline__ void red4(float4* addr, float a, float b, float c, float d) {
    asm volatile("red.global.add.v4.f32 [%0], {%1,%2,%3,%4};"
                 :: "l"(addr), "f"(a), "f"(b), "f"(c), "f"(d) : "memory");
}

// ---------------- init: reset stats, deg = 2 (self loop weight) ----------------
__global__ void k_init() {
    int i = blockIdx.x * 256 + threadIdx.x;
    if (i < Nn) { d_degP[i] = 2.0f; d_degG[i] = 2.0f; }
    if (blockIdx.x == 0) {
        int t = threadIdx.x;
        if (t < 64) { d_sum1[t] = 0.f; d_ssq1[t] = 0.f; }
        else if (t < 96) { d_sum2[t - 64] = 0.f; d_ssq2[t - 64] = 0.f; }
    }
}

// ---------------- degrees over src ----------------
__global__ void k_deg(const int* __restrict__ src, const float* __restrict__ ppmi) {
    int e = blockIdx.x * 256 + threadIdx.x;
    if (e >= Ee) return;
    int s = src[e];
    atomicAdd(&d_degG[s], 1.0f);
    atomicAdd(&d_degP[s], ppmi[e]);
}

__global__ void k_dinv() {
    int i = blockIdx.x * 256 + threadIdx.x;
    if (i >= Nn) return;
    d_degP[i] = rsqrtf(d_degP[i]);
    d_degG[i] = rsqrtf(d_degG[i]);
}

// ---------------- GEMM1: tmp1 = x@W1 + b1 (+stats) ----------------
__global__ void k_gemm1(const float* __restrict__ x, const float* __restrict__ W1,
                        const float* __restrict__ b1) {
    __shared__ float xs[64][33];
    __shared__ float ws[32][65];
    __shared__ float ssum[64], ssq[64];
    int t = threadIdx.x;
    int row0 = blockIdx.x * 64;
    int ty = t >> 4, tx = t & 15;
    float acc[4][4] = {};
    for (int kc = 0; kc < 256; kc += 32) {
        #pragma unroll
        for (int i = 0; i < 8; i++) {
            int idx = t + i * 256;
            int r = idx >> 5, k = idx & 31;
            int gr = row0 + r;
            xs[r][k] = (gr < Nn) ? x[gr * 256 + kc + k] : 0.f;
        }
        #pragma unroll
        for (int i = 0; i < 8; i++) {
            int idx = t + i * 256;
            int k = idx >> 6, c = idx & 63;
            ws[k][c] = W1[(kc + k) * 64 + c];
        }
        __syncthreads();
        #pragma unroll
        for (int kk = 0; kk < 32; kk++) {
            float a[4], b[4];
            #pragma unroll
            for (int i = 0; i < 4; i++) a[i] = xs[ty * 4 + i][kk];
            #pragma unroll
            for (int j = 0; j < 4; j++) b[j] = ws[kk][tx * 4 + j];
            #pragma unroll
            for (int i = 0; i < 4; i++)
                #pragma unroll
                for (int j = 0; j < 4; j++) acc[i][j] += a[i] * b[j];
        }
        __syncthreads();
    }
    if (t < 64) { ssum[t] = 0.f; ssq[t] = 0.f; }
    __syncthreads();
    #pragma unroll
    for (int i = 0; i < 4; i++) {
        int gr = row0 + ty * 4 + i;
        if (gr < Nn) {
            #pragma unroll
            for (int j = 0; j < 4; j++) {
                int c = tx * 4 + j;
                float v = acc[i][j] + b1[c];
                d_tmp1[gr * 64 + c] = v;
                atomicAdd(&ssum[c], v);
                atomicAdd(&ssq[c], v * v);
            }
        }
    }
    __syncthreads();
    if (t < 64) { atomicAdd(&d_sum1[t], ssum[t]); atomicAdd(&d_ssq1[t], ssq[t]); }
}

__global__ void k_stats1() {
    int t = threadIdx.x;  // 64
    float m = d_sum1[t] / (float)Nn;
    float v = d_ssq1[t] / (float)Nn - m * m;
    d_mean1[t] = m;
    d_rstd1[t] = rsqrtf(v + 1e-3f);
}

// ---------------- GEMM2: tmp2 = elu(bn(tmp1))@W2 + b2 (+stats) ----------------
__global__ void k_gemm2(const float* __restrict__ W2, const float* __restrict__ b2,
                        const float* __restrict__ g1, const float* __restrict__ be1) {
    __shared__ float es[64][65];
    __shared__ float ws2[64][33];
    __shared__ float ssum[32], ssq[32];
    int t = threadIdx.x;
    int row0 = blockIdx.x * 64;
    #pragma unroll
    for (int i = 0; i < 16; i++) {
        int idx = t + i * 256;
        int r = idx >> 6, c = idx & 63;
        int gr = row0 + r;
        float v = (gr < Nn) ? d_tmp1[gr * 64 + c] : 0.f;
        es[r][c] = elu_f(g1[c] * (v - d_mean1[c]) * d_rstd1[c] + be1[c]);
    }
    #pragma unroll
    for (int i = 0; i < 8; i++) {
        int idx = t + i * 256;
        int k = idx >> 5, c = idx & 31;
        ws2[k][c] = W2[k * 32 + c];
    }
    if (t < 32) { ssum[t] = 0.f; ssq[t] = 0.f; }
    __syncthreads();
    int c = t & 31, r0 = t >> 5;  // r0 in 0..7
    float acc[8] = {};
    for (int k = 0; k < 64; k++) {
        float b = ws2[k][c];
        #pragma unroll
        for (int i = 0; i < 8; i++) acc[i] += es[r0 + 8 * i][k] * b;
    }
    #pragma unroll
    for (int i = 0; i < 8; i++) {
        int gr = row0 + r0 + 8 * i;
        if (gr < Nn) {
            float v = acc[i] + b2[c];
            d_tmp2[gr * 32 + c] = v;
            atomicAdd(&ssum[c], v);
            atomicAdd(&ssq[c], v * v);
        }
    }
    __syncthreads();
    if (t < 32) { atomicAdd(&d_sum2[t], ssum[t]); atomicAdd(&d_ssq2[t], ssq[t]); }
}

__global__ void k_stats2() {
    int t = threadIdx.x;  // 32
    float m = d_sum2[t] / (float)Nn;
    float v = d_ssq2[t] / (float)Nn - m * m;
    d_mean2[t] = m;
    d_rstd2[t] = rsqrtf(v + 1e-3f);
}

// ---------------- h1 = emb@Wg1; init conv1 accumulators with bias + self loop ----------------
__global__ void k_h1(const float* __restrict__ Wg1, const float* __restrict__ bg1,
                     const float* __restrict__ g2, const float* __restrict__ be2) {
    __shared__ float es[64][33];
    __shared__ float wg[32][33];
    __shared__ float dp2[64], dg2[64];
    int t = threadIdx.x;
    int row0 = blockIdx.x * 64;
    #pragma unroll
    for (int i = 0; i < 8; i++) {
        int idx = t + i * 256;
        int r = idx >> 5, c = idx & 31;
        int gr = row0 + r;
        float v = (gr < Nn) ? d_tmp2[gr * 32 + c] : 0.f;
        es[r][c] = elu_f(g2[c] * (v - d_mean2[c]) * d_rstd2[c] + be2[c]);
    }
    #pragma unroll
    for (int i = 0; i < 4; i++) {
        int idx = t + i * 256;
        wg[idx >> 5][idx & 31] = Wg1[idx];
    }
    if (t < 64) {
        int gr = row0 + t;
        float dp = (gr < Nn) ? d_degP[gr] : 0.f;
        float dg = (gr < Nn) ? d_degG[gr] : 0.f;
        dp2[t] = 2.f * dp * dp;
        dg2[t] = 2.f * dg * dg;
    }
    __syncthreads();
    int c = t & 31, r0 = t >> 5;
    #pragma unroll
    for (int i = 0; i < 8; i++) {
        int r = r0 + 8 * i;
        int gr = row0 + r;
        if (gr >= Nn) continue;
        float acc = 0.f;
        #pragma unroll
        for (int k = 0; k < 32; k++) acc += es[r][k] * wg[k][c];
        d_h1[gr * 32 + c] = acc;
        d_aggP[gr * 32 + c] = bg1[c] + dp2[r] * acc;
        d_aggA[gr * 32 + c] = bg1[c] + dg2[r] * acc;
    }
}

// ---------------- edge pass 1: scatter h1 with both norms ----------------
__global__ void k_edge1(const int* __restrict__ src, const int* __restrict__ dst,
                        const float* __restrict__ ppmi) {
    int gtid = blockIdx.x * 256 + threadIdx.x;
    int e = gtid >> 3;
    int q = gtid & 7;
    int lane = threadIdx.x & 31;
    int base = lane & 24;
    int r = 0, c = 0;
    float np = 0.f, ng = 0.f;
    if (q == 0) {
        r = src[e]; c = dst[e];
        float w = ppmi[e];
        float dpr = d_degP[r], dpc = d_degP[c];
        float dgr = d_degG[r], dgc = d_degG[c];
        np = dpr * w * dpc;
        ng = dgr * dgc;
    }
    r = __shfl_sync(0xffffffffu, r, base);
    c = __shfl_sync(0xffffffffu, c, base);
    np = __shfl_sync(0xffffffffu, np, base);
    ng = __shfl_sync(0xffffffffu, ng, base);
    float4 v = reinterpret_cast<const float4*>(d_h1)[r * 8 + q];
    red4(&reinterpret_cast<float4*>(d_aggP)[c * 8 + q], np * v.x, np * v.y, np * v.z, np * v.w);
    red4(&reinterpret_cast<float4*>(d_aggA)[c * 8 + q], ng * v.x, ng * v.y, ng * v.z, ng * v.w);
}

// ---------------- feature = relu(agg); hcat = feature@[Wg2|Wg3]; init acc2 ----------------
__global__ void k_feat(const float* __restrict__ Wg2, const float* __restrict__ bg2,
                       const float* __restrict__ Wg3, const float* __restrict__ bg3) {
    __shared__ float fps[64][33], fas[64][33];
    __shared__ float w23[32][66];  // col<32: Wg2, col>=32: Wg3 (padded 66)
    __shared__ float dp2[64], dg2[64];
    int t = threadIdx.x;
    int row0 = blockIdx.x * 64;
    #pragma unroll
    for (int i = 0; i < 8; i++) {
        int idx = t + i * 256;
        int r = idx >> 5, c = idx & 31;
        int gr = row0 + r;
        float vp = (gr < Nn) ? d_aggP[gr * 32 + c] : 0.f;
        float va = (gr < Nn) ? d_aggA[gr * 32 + c] : 0.f;
        vp = fmaxf(vp, 0.f);
        va = fmaxf(va, 0.f);
        fps[r][c] = vp;
        fas[r][c] = va;
        if (gr < Nn) { d_fp[gr * 32 + c] = vp; d_fa[gr * 32 + c] = va; }
    }
    #pragma unroll
    for (int i = 0; i < 4; i++) {
        int idx = t + i * 256;
        int k = idx >> 5, c = idx & 31;
        w23[k][c] = Wg2[k * 32 + c];
        w23[k][32 + c] = Wg3[k * 32 + c];
    }
    if (t < 64) {
        int gr = row0 + t;
        float dp = (gr < Nn) ? d_degP[gr] : 0.f;
        float dg = (gr < Nn) ? d_degG[gr] : 0.f;
        dp2[t] = 2.f * dp * dp;
        dg2[t] = 2.f * dg * dg;
    }
    __syncthreads();
    int c = t & 63, r0 = t >> 6;  // r0 in 0..3
    float bias = (c < 32) ? bg2[c] : bg3[c - 32];
    #pragma unroll
    for (int i = 0; i < 16; i++) {
        int r = r0 + 4 * i;
        int gr = row0 + r;
        if (gr >= Nn) continue;
        float hp = 0.f, ha = 0.f;
        #pragma unroll
        for (int k = 0; k < 32; k++) {
            float wv = w23[k][c];
            hp += fps[r][k] * wv;
            ha += fas[r][k] * wv;
        }
        d_hcatP[gr * 64 + c] = hp;
        d_hcatA[gr * 64 + c] = ha;
        d_acc2P[gr * 64 + c] = bias + dp2[r] * hp;
        d_acc2A[gr * 64 + c] = bias + dg2[r] * ha;
    }
}

// ---------------- edge pass 2: scatter hcatP (ppmi) and hcatA (gcn) ----------------
__global__ void k_edge2(const int* __restrict__ src, const int* __restrict__ dst,
                        const float* __restrict__ ppmi) {
    int gtid = blockIdx.x * 256 + threadIdx.x;
    int e = gtid >> 5;
    int lane = threadIdx.x & 31;
    int r = 0, c = 0;
    float np = 0.f, ng = 0.f;
    if (lane == 0) {
        r = src[e]; c = dst[e];
        float w = ppmi[e];
        float dpr = d_degP[r], dpc = d_degP[c];
        float dgr = d_degG[r], dgc = d_degG[c];
        np = dpr * w * dpc;
        ng = dgr * dgc;
    }
    r = __shfl_sync(0xffffffffu, r, 0);
    c = __shfl_sync(0xffffffffu, c, 0);
    np = __shfl_sync(0xffffffffu, np, 0);
    ng = __shfl_sync(0xffffffffu, ng, 0);
    if (lane < 16) {
        float4 v = reinterpret_cast<const float4*>(d_hcatP)[r * 16 + lane];
        red4(&reinterpret_cast<float4*>(d_acc2P)[c * 16 + lane],
             np * v.x, np * v.y, np * v.z, np * v.w);
    } else {
        int q = lane - 16;
        float4 v = reinterpret_cast<const float4*>(d_hcatA)[r * 16 + q];
        red4(&reinterpret_cast<float4*>(d_acc2A)[c * 16 + q],
             ng * v.x, ng * v.y, ng * v.z, ng * v.w);
    }
}

// ---------------- reparameterize + attention fusion + output ----------------
__device__ __forceinline__ float warp_sum(float v) {
    #pragma unroll
    for (int o = 16; o > 0; o >>= 1) v += __shfl_xor_sync(0xffffffffu, v, o);
    return v;
}

__global__ void k_out(const float* __restrict__ noise_p, const float* __restrict__ noise_a,
                      const float* __restrict__ Watt, const float* __restrict__ batt,
                      float* __restrict__ out) {
    int gtid = blockIdx.x * 256 + threadIdx.x;
    int n = gtid >> 5;
    int lane = threadIdx.x & 31;
    if (n >= Nn) return;
    float fpv = d_fp[n * 32 + lane];
    float fav = d_fa[n * 32 + lane];
    float mup = d_acc2P[n * 64 + lane];
    float lvp = d_acc2P[n * 64 + 32 + lane];
    float mua = d_acc2A[n * 64 + lane];
    float lva = d_acc2A[n * 64 + 32 + lane];
    float zp = noise_p[n * 32 + lane] * expf(lvp) + mup;
    float za = noise_a[n * 32 + lane] * expf(lva) + mua;
    float wv = Watt[lane];
    float b0 = batt[0];
    float la = warp_sum(fpv * wv) + b0;
    float lb = warp_sum(fav * wv) + b0;
    float lc = warp_sum(zp * wv) + b0;
    float ld = warp_sum(za * wv) + b0;
    // softmax over pairs
    float m1 = fmaxf(la, lb);
    float ea = expf(la - m1), eb = expf(lb - m1);
    float wa = ea / (ea + eb);
    float zf = wa * fpv + (1.f - wa) * fav;
    float m2 = fmaxf(lc, ld);
    float ec = expf(lc - m2), ed = expf(ld - m2);
    float wc = ec / (ec + ed);
    float zg = wc * zp + (1.f - wc) * za;
    out[n * 64 + lane] = zf;
    out[n * 64 + 32 + lane] = zg;
}

// ---------------- launch ----------------
extern "C" void kernel_launch(void* const* d_in, const int* in_sizes, int n_in,
                              void* d_out, int out_size) {
    const float* x       = (const float*)d_in[0];
    const int*   eidx    = (const int*)d_in[1];
    const float* ppmi    = (const float*)d_in[2];
    const float* noise_p = (const float*)d_in[3];
    const float* noise_a = (const float*)d_in[4];
    const float* W1  = (const float*)d_in[5];
    const float* b1  = (const float*)d_in[6];
    const float* g1  = (const float*)d_in[7];
    const float* be1 = (const float*)d_in[8];
    const float* W2  = (const float*)d_in[9];
    const float* b2  = (const float*)d_in[10];
    const float* g2  = (const float*)d_in[11];
    const float* be2 = (const float*)d_in[12];
    const float* Wg1 = (const float*)d_in[13];
    const float* bg1 = (const float*)d_in[14];
    const float* Wg2 = (const float*)d_in[15];
    const float* bg2 = (const float*)d_in[16];
    const float* Wg3 = (const float*)d_in[17];
    const float* bg3 = (const float*)d_in[18];
    const float* Watt = (const float*)d_in[19];
    const float* batt = (const float*)d_in[20];
    float* out = (float*)d_out;

    const int* src = eidx;        // edge_index[0]
    const int* dst = eidx + Ee;   // edge_index[1]

    int nblkN = (Nn + 255) / 256;
    int nblk64 = (Nn + 63) / 64;

    k_init<<<nblkN, 256>>>();
    k_deg<<<(Ee + 255) / 256, 256>>>(src, ppmi);
    k_dinv<<<nblkN, 256>>>();
    k_gemm1<<<nblk64, 256>>>(x, W1, b1);
    k_stats1<<<1, 64>>>();
    k_gemm2<<<nblk64, 256>>>(W2, b2, g1, be1);
    k_stats2<<<1, 32>>>();
    k_h1<<<nblk64, 256>>>(Wg1, bg1, g2, be2);
    k_edge1<<<(Ee * 8) / 256, 256>>>(src, dst, ppmi);
    k_feat<<<nblk64, 256>>>(Wg2, bg2, Wg3, bg3);
    k_edge2<<<(Ee * 32) / 256, 256>>>(src, dst, ppmi);
    k_out<<<(Nn * 32 + 255) / 256, 256>>>(noise_p, noise_a, Watt, batt, out);
}

// round 2
// speedup vs baseline: 1.6414x; 1.6414x over previous
#include <cuda_runtime.h>
#include <cuda_bf16.h>

#define Nn 100000
#define Ee 2400000

// ---------------- device scratch (static, no allocation) ----------------
__device__ __align__(16) float d_tmp1[Nn * 64];   // x@W1+b1
__device__ __align__(16) float d_tmp2[Nn * 32];   // e1@W2+b2
__device__ __align__(16) float d_h1[Nn * 32];     // emb@Wg1
__device__ __align__(16) float d_fp[Nn * 32];     // relu(conv1 ppmi)
__device__ __align__(16) float d_fa[Nn * 32];     // relu(conv1 gcn)
__device__ __align__(16) float d_hcatP[Nn * 64];  // fp@[Wg2|Wg3]
__device__ __align__(16) float d_hcatA[Nn * 64];  // fa@[Wg2|Wg3]
__device__ float d_degP[Nn];
__device__ float d_degG[Nn];
__device__ int   d_cnt[Nn];
__device__ int   d_off[Nn + 1];
__device__ int   d_pos[Nn];
__device__ int   d_bsum[128];
__device__ int   d_boff[128];
__device__ __align__(16) int   d_ssrc[Ee];
__device__ __align__(16) float d_snp[Ee];
__device__ __align__(16) float d_sng[Ee];
__device__ float d_sum1[64], d_ssq1[64];
__device__ float d_sum2[32], d_ssq2[32];
__device__ float d_mean1[64], d_rstd1[64];
__device__ float d_mean2[32], d_rstd2[32];

__device__ __forceinline__ float elu_f(float x) { return x > 0.f ? x : expm1f(x); }

__device__ __forceinline__ float warp_sum(float v) {
    #pragma unroll
    for (int o = 16; o > 0; o >>= 1) v += __shfl_xor_sync(0xffffffffu, v, o);
    return v;
}

// ---------------- init ----------------
__global__ void k_init() {
    int i = blockIdx.x * 256 + threadIdx.x;
    if (i < Nn) { d_degP[i] = 2.0f; d_degG[i] = 2.0f; d_cnt[i] = 0; }
    if (blockIdx.x == 0) {
        int t = threadIdx.x;
        if (t < 64) { d_sum1[t] = 0.f; d_ssq1[t] = 0.f; }
        else if (t < 96) { d_sum2[t - 64] = 0.f; d_ssq2[t - 64] = 0.f; }
    }
}

// ---------------- degree (over src) + dst histogram ----------------
__global__ void k_deg(const int* __restrict__ src, const int* __restrict__ dst,
                      const float* __restrict__ ppmi) {
    int e = blockIdx.x * 256 + threadIdx.x;
    if (e >= Ee) return;
    int s = src[e];
    atomicAdd(&d_degG[s], 1.0f);
    atomicAdd(&d_degP[s], ppmi[e]);
    atomicAdd(&d_cnt[dst[e]], 1);
}

__global__ void k_dinv() {
    int i = blockIdx.x * 256 + threadIdx.x;
    if (i >= Nn) return;
    d_degP[i] = rsqrtf(d_degP[i]);
    d_degG[i] = rsqrtf(d_degG[i]);
}

// ---------------- 3-step exclusive scan of d_cnt -> d_off ----------------
__global__ void k_scan1() {
    __shared__ int wsum[32];
    int b = blockIdx.x, t = threadIdx.x;
    int i = b * 1024 + t;
    int lane = t & 31, wid = t >> 5;
    int c = (i < Nn) ? d_cnt[i] : 0;
    int v = c;
    #pragma unroll
    for (int d = 1; d < 32; d <<= 1) {
        int u = __shfl_up_sync(0xffffffffu, v, d);
        if (lane >= d) v += u;
    }
    if (lane == 31) wsum[wid] = v;
    __syncthreads();
    if (wid == 0) {
        int s = wsum[lane];
        #pragma unroll
        for (int d = 1; d < 32; d <<= 1) {
            int u = __shfl_up_sync(0xffffffffu, s, d);
            if (lane >= d) s += u;
        }
        wsum[lane] = s;
    }
    __syncthreads();
    int incl = v + (wid > 0 ? wsum[wid - 1] : 0);
    if (i < Nn) d_off[i] = incl - c;   // exclusive within block
    if (t == 1023) d_bsum[b] = incl;
}

__global__ void k_scan2(int nblk) {
    if (threadIdx.x == 0) {
        int run = 0;
        for (int b = 0; b < nblk; b++) { d_boff[b] = run; run += d_bsum[b]; }
        d_off[Nn] = Ee;
    }
}

__global__ void k_scan3() {
    int i = blockIdx.x * 256 + threadIdx.x;
    if (i >= Nn) return;
    int v = d_off[i] + d_boff[i >> 10];
    d_off[i] = v;
    d_pos[i] = v;
}

// ---------------- reorder edges by dst; precompute norms ----------------
__global__ void k_reorder(const int* __restrict__ src, const int* __restrict__ dst,
                          const float* __restrict__ ppmi) {
    int e = blockIdx.x * 256 + threadIdx.x;
    if (e >= Ee) return;
    int s = src[e], d = dst[e];
    float w = ppmi[e];
    float np = d_degP[s] * w * d_degP[d];
    float ng = d_degG[s] * d_degG[d];
    int p = atomicAdd(&d_pos[d], 1);
    d_ssrc[p] = s;
    d_snp[p] = np;
    d_sng[p] = ng;
}

// ---------------- GEMM1: tmp1 = x@W1 + b1 (+stats) ----------------
// 64-row tile, warp w -> cols [8w,8w+8), lane -> rows {lane, lane+32}
__global__ void k_gemm1(const float* __restrict__ x, const float* __restrict__ W1,
                        const float* __restrict__ b1) {
    __shared__ float xs[64][68];
    __shared__ float Ws[64][64];
    __shared__ float ssum[64], ssq[64];
    int t = threadIdx.x;
    int lane = t & 31, w = t >> 5;
    int row0 = blockIdx.x * 64;
    float acc0[8] = {}, acc1[8] = {};
    for (int kc = 0; kc < 256; kc += 64) {
        #pragma unroll
        for (int i = 0; i < 4; i++) {
            int idx = t + i * 256;
            int r = idx >> 4, kq = idx & 15;
            int gr = row0 + r;
            float4 v = (gr < Nn) ? *(const float4*)&x[gr * 256 + kc + kq * 4]
                                 : make_float4(0.f, 0.f, 0.f, 0.f);
            *(float4*)&xs[r][kq * 4] = v;
        }
        #pragma unroll
        for (int i = 0; i < 4; i++) {
            int idx = t + i * 256;
            int k = idx >> 4, cq = idx & 15;
            *(float4*)&Ws[k][cq * 4] = *(const float4*)&W1[(kc + k) * 64 + cq * 4];
        }
        __syncthreads();
        #pragma unroll
        for (int kk = 0; kk < 64; kk += 4) {
            float a0v[4], a1v[4];
            *(float4*)a0v = *(const float4*)&xs[lane][kk];
            *(float4*)a1v = *(const float4*)&xs[lane + 32][kk];
            #pragma unroll
            for (int m = 0; m < 4; m++) {
                float bv[8];
                *(float4*)&bv[0] = *(const float4*)&Ws[kk + m][w * 8];
                *(float4*)&bv[4] = *(const float4*)&Ws[kk + m][w * 8 + 4];
                #pragma unroll
                for (int j = 0; j < 8; j++) {
                    acc0[j] += a0v[m] * bv[j];
                    acc1[j] += a1v[m] * bv[j];
                }
            }
        }
        __syncthreads();
    }
    if (t < 64) { ssum[t] = 0.f; ssq[t] = 0.f; }
    __syncthreads();
    int gr0 = row0 + lane, gr1 = row0 + lane + 32;
    float v0[8], v1[8];
    #pragma unroll
    for (int j = 0; j < 8; j++) {
        float bv = b1[w * 8 + j];
        v0[j] = acc0[j] + bv;
        v1[j] = acc1[j] + bv;
    }
    if (gr0 < Nn) {
        *(float4*)&d_tmp1[gr0 * 64 + w * 8]     = *(float4*)&v0[0];
        *(float4*)&d_tmp1[gr0 * 64 + w * 8 + 4] = *(float4*)&v0[4];
    }
    if (gr1 < Nn) {
        *(float4*)&d_tmp1[gr1 * 64 + w * 8]     = *(float4*)&v1[0];
        *(float4*)&d_tmp1[gr1 * 64 + w * 8 + 4] = *(float4*)&v1[4];
    }
    #pragma unroll
    for (int j = 0; j < 8; j++) {
        float a = (gr0 < Nn) ? v0[j] : 0.f;
        float b = (gr1 < Nn) ? v1[j] : 0.f;
        float s = warp_sum(a + b);
        float q = warp_sum(a * a + b * b);
        if (lane == 0) { atomicAdd(&ssum[w * 8 + j], s); atomicAdd(&ssq[w * 8 + j], q); }
    }
    __syncthreads();
    if (t < 64) { atomicAdd(&d_sum1[t], ssum[t]); atomicAdd(&d_ssq1[t], ssq[t]); }
}

__global__ void k_stats1() {
    int t = threadIdx.x;  // 64
    float m = d_sum1[t] / (float)Nn;
    float v = d_ssq1[t] / (float)Nn - m * m;
    d_mean1[t] = m;
    d_rstd1[t] = rsqrtf(v + 1e-3f);
}

// ---------------- GEMM2: tmp2 = elu(bn(tmp1))@W2 + b2 (+stats) ----------------
__global__ void k_gemm2(const float* __restrict__ W2, const float* __restrict__ b2,
                        const float* __restrict__ g1, const float* __restrict__ be1) {
    __shared__ float es[64][65];
    __shared__ float ws2[64][33];
    __shared__ float ssum[32], ssq[32];
    int t = threadIdx.x;
    int row0 = blockIdx.x * 64;
    #pragma unroll
    for (int i = 0; i < 16; i++) {
        int idx = t + i * 256;
        int r = idx >> 6, c = idx & 63;
        int gr = row0 + r;
        float v = (gr < Nn) ? d_tmp1[gr * 64 + c] : 0.f;
        es[r][c] = elu_f(g1[c] * (v - d_mean1[c]) * d_rstd1[c] + be1[c]);
    }
    #pragma unroll
    for (int i = 0; i < 8; i++) {
        int idx = t + i * 256;
        int k = idx >> 5, c = idx & 31;
        ws2[k][c] = W2[k * 32 + c];
    }
    if (t < 32) { ssum[t] = 0.f; ssq[t] = 0.f; }
    __syncthreads();
    int c = t & 31, r0 = t >> 5;
    float acc[8] = {};
    for (int k = 0; k < 64; k++) {
        float b = ws2[k][c];
        #pragma unroll
        for (int i = 0; i < 8; i++) acc[i] += es[r0 + 8 * i][k] * b;
    }
    #pragma unroll
    for (int i = 0; i < 8; i++) {
        int gr = row0 + r0 + 8 * i;
        if (gr < Nn) {
            float v = acc[i] + b2[c];
            d_tmp2[gr * 32 + c] = v;
            atomicAdd(&ssum[c], v);
            atomicAdd(&ssq[c], v * v);
        }
    }
    __syncthreads();
    if (t < 32) { atomicAdd(&d_sum2[t], ssum[t]); atomicAdd(&d_ssq2[t], ssq[t]); }
}

__global__ void k_stats2() {
    int t = threadIdx.x;  // 32
    float m = d_sum2[t] / (float)Nn;
    float v = d_ssq2[t] / (float)Nn - m * m;
    d_mean2[t] = m;
    d_rstd2[t] = rsqrtf(v + 1e-3f);
}

// ---------------- h1 = elu(bn(tmp2))@Wg1 ----------------
__global__ void k_h1(const float* __restrict__ Wg1, const float* __restrict__ g2,
                     const float* __restrict__ be2) {
    __shared__ float es[64][33];
    __shared__ float wg[32][33];
    int t = threadIdx.x;
    int row0 = blockIdx.x * 64;
    #pragma unroll
    for (int i = 0; i < 8; i++) {
        int idx = t + i * 256;
        int r = idx >> 5, c = idx & 31;
        int gr = row0 + r;
        float v = (gr < Nn) ? d_tmp2[gr * 32 + c] : 0.f;
        es[r][c] = elu_f(g2[c] * (v - d_mean2[c]) * d_rstd2[c] + be2[c]);
    }
    #pragma unroll
    for (int i = 0; i < 4; i++) {
        int idx = t + i * 256;
        wg[idx >> 5][idx & 31] = Wg1[idx];
    }
    __syncthreads();
    int c = t & 31, r0 = t >> 5;
    #pragma unroll
    for (int i = 0; i < 8; i++) {
        int r = r0 + 8 * i;
        int gr = row0 + r;
        if (gr >= Nn) continue;
        float acc = 0.f;
        #pragma unroll
        for (int k = 0; k < 32; k++) acc += es[r][k] * wg[k][c];
        d_h1[gr * 32 + c] = acc;
    }
}

// ---------------- conv1: warp-per-node segment reduction over sorted edges ----------------
__global__ void k_conv1(const float* __restrict__ bg1) {
    int gw = blockIdx.x * 8 + (threadIdx.x >> 5);
    int lane = threadIdx.x & 31;
    if (gw >= Nn) return;
    int n = gw;
    int beg = d_off[n], end = d_off[n + 1];
    float dp = d_degP[n], dg = d_degG[n];
    float self = d_h1[n * 32 + lane];
    float bias = bg1[lane];
    float accp = bias + 2.f * dp * dp * self;
    float acca = bias + 2.f * dg * dg * self;
    int j = beg;
    for (; j + 4 <= end; j += 4) {
        int s0 = d_ssrc[j], s1 = d_ssrc[j + 1], s2 = d_ssrc[j + 2], s3 = d_ssrc[j + 3];
        float np0 = d_snp[j], np1 = d_snp[j + 1], np2 = d_snp[j + 2], np3 = d_snp[j + 3];
        float ng0 = d_sng[j], ng1 = d_sng[j + 1], ng2 = d_sng[j + 2], ng3 = d_sng[j + 3];
        float v0 = d_h1[s0 * 32 + lane];
        float v1 = d_h1[s1 * 32 + lane];
        float v2 = d_h1[s2 * 32 + lane];
        float v3 = d_h1[s3 * 32 + lane];
        accp += np0 * v0 + np1 * v1 + np2 * v2 + np3 * v3;
        acca += ng0 * v0 + ng1 * v1 + ng2 * v2 + ng3 * v3;
    }
    for (; j < end; j++) {
        int s = d_ssrc[j];
        float v = d_h1[s * 32 + lane];
        accp += d_snp[j] * v;
        acca += d_sng[j] * v;
    }
    d_fp[n * 32 + lane] = fmaxf(accp, 0.f);
    d_fa[n * 32 + lane] = fmaxf(acca, 0.f);
}

// ---------------- hcat = feature@[Wg2|Wg3] ----------------
__global__ void k_feat(const float* __restrict__ Wg2, const float* __restrict__ Wg3) {
    __shared__ float fps[64][33], fas[64][33];
    __shared__ float w23[32][66];
    int t = threadIdx.x;
    int row0 = blockIdx.x * 64;
    #pragma unroll
    for (int i = 0; i < 8; i++) {
        int idx = t + i * 256;
        int r = idx >> 5, c = idx & 31;
        int gr = row0 + r;
        fps[r][c] = (gr < Nn) ? d_fp[gr * 32 + c] : 0.f;
        fas[r][c] = (gr < Nn) ? d_fa[gr * 32 + c] : 0.f;
    }
    #pragma unroll
    for (int i = 0; i < 4; i++) {
        int idx = t + i * 256;
        int k = idx >> 5, c = idx & 31;
        w23[k][c] = Wg2[k * 32 + c];
        w23[k][32 + c] = Wg3[k * 32 + c];
    }
    __syncthreads();
    int c = t & 63, r0 = t >> 6;
    #pragma unroll
    for (int i = 0; i < 16; i++) {
        int r = r0 + 4 * i;
        int gr = row0 + r;
        if (gr >= Nn) continue;
        float hp = 0.f, ha = 0.f;
        #pragma unroll
        for (int k = 0; k < 32; k++) {
            float wv = w23[k][c];
            hp += fps[r][k] * wv;
            ha += fas[r][k] * wv;
        }
        d_hcatP[gr * 64 + c] = hp;
        d_hcatA[gr * 64 + c] = ha;
    }
}

// ---------------- conv2 + reparam + attention + output (fully fused) ----------------
__global__ void k_conv2out(const float* __restrict__ noise_p, const float* __restrict__ noise_a,
                           const float* __restrict__ Watt, const float* __restrict__ batt,
                           const float* __restrict__ bg2, const float* __restrict__ bg3,
                           float* __restrict__ out) {
    int gw = blockIdx.x * 8 + (threadIdx.x >> 5);
    int lane = threadIdx.x & 31;
    if (gw >= Nn) return;
    int n = gw;
    int beg = d_off[n], end = d_off[n + 1];
    float dp = d_degP[n], dg = d_degG[n];
    float sp2 = 2.f * dp * dp, sg2 = 2.f * dg * dg;
    float b2v = bg2[lane], b3v = bg3[lane];
    float mup = b2v + sp2 * d_hcatP[n * 64 + lane];
    float lvp = b3v + sp2 * d_hcatP[n * 64 + 32 + lane];
    float mua = b2v + sg2 * d_hcatA[n * 64 + lane];
    float lva = b3v + sg2 * d_hcatA[n * 64 + 32 + lane];
    int j = beg;
    for (; j + 2 <= end; j += 2) {
        int s0 = d_ssrc[j], s1 = d_ssrc[j + 1];
        float np0 = d_snp[j], np1 = d_snp[j + 1];
        float ng0 = d_sng[j], ng1 = d_sng[j + 1];
        float p0m = d_hcatP[s0 * 64 + lane], p0l = d_hcatP[s0 * 64 + 32 + lane];
        float a0m = d_hcatA[s0 * 64 + lane], a0l = d_hcatA[s0 * 64 + 32 + lane];
        float p1m = d_hcatP[s1 * 64 + lane], p1l = d_hcatP[s1 * 64 + 32 + lane];
        float a1m = d_hcatA[s1 * 64 + lane], a1l = d_hcatA[s1 * 64 + 32 + lane];
        mup += np0 * p0m + np1 * p1m;
        lvp += np0 * p0l + np1 * p1l;
        mua += ng0 * a0m + ng1 * a1m;
        lva += ng0 * a0l + ng1 * a1l;
    }
    for (; j < end; j++) {
        int s = d_ssrc[j];
        float np = d_snp[j], ng = d_sng[j];
        mup += np * d_hcatP[s * 64 + lane];
        lvp += np * d_hcatP[s * 64 + 32 + lane];
        mua += ng * d_hcatA[s * 64 + lane];
        lva += ng * d_hcatA[s * 64 + 32 + lane];
    }
    float fpv = d_fp[n * 32 + lane];
    float fav = d_fa[n * 32 + lane];
    float zp = noise_p[n * 32 + lane] * expf(lvp) + mup;
    float za = noise_a[n * 32 + lane] * expf(lva) + mua;
    float wv = Watt[lane];
    float b0 = batt[0];
    float la = warp_sum(fpv * wv) + b0;
    float lb = warp_sum(fav * wv) + b0;
    float lc = warp_sum(zp * wv) + b0;
    float ld = warp_sum(za * wv) + b0;
    float m1 = fmaxf(la, lb);
    float ea = expf(la - m1), eb = expf(lb - m1);
    float wa = ea / (ea + eb);
    float zf = wa * fpv + (1.f - wa) * fav;
    float m2 = fmaxf(lc, ld);
    float ec = expf(lc - m2), ed = expf(ld - m2);
    float wc = ec / (ec + ed);
    float zg = wc * zp + (1.f - wc) * za;
    out[n * 64 + lane] = zf;
    out[n * 64 + 32 + lane] = zg;
}

// ---------------- launch ----------------
extern "C" void kernel_launch(void* const* d_in, const int* in_sizes, int n_in,
                              void* d_out, int out_size) {
    const float* x       = (const float*)d_in[0];
    const int*   eidx    = (const int*)d_in[1];
    const float* ppmi    = (const float*)d_in[2];
    const float* noise_p = (const float*)d_in[3];
    const float* noise_a = (const float*)d_in[4];
    const float* W1  = (const float*)d_in[5];
    const float* b1  = (const float*)d_in[6];
    const float* g1  = (const float*)d_in[7];
    const float* be1 = (const float*)d_in[8];
    const float* W2  = (const float*)d_in[9];
    const float* b2  = (const float*)d_in[10];
    const float* g2  = (const float*)d_in[11];
    const float* be2 = (const float*)d_in[12];
    const float* Wg1 = (const float*)d_in[13];
    const float* bg1 = (const float*)d_in[14];
    const float* Wg2 = (const float*)d_in[15];
    const float* bg2 = (const float*)d_in[16];
    const float* Wg3 = (const float*)d_in[17];
    const float* bg3 = (const float*)d_in[18];
    const float* Watt = (const float*)d_in[19];
    const float* batt = (const float*)d_in[20];
    float* out = (float*)d_out;

    const int* src = eidx;        // edge_index[0]
    const int* dst = eidx + Ee;   // edge_index[1]

    int nblkN = (Nn + 255) / 256;
    int nblk64 = (Nn + 63) / 64;
    int nscan = (Nn + 1023) / 1024;
    int nwarp = (Nn + 7) / 8;

    k_init<<<nblkN, 256>>>();
    k_deg<<<(Ee + 255) / 256, 256>>>(src, dst, ppmi);
    k_dinv<<<nblkN, 256>>>();
    k_scan1<<<nscan, 1024>>>();
    k_scan2<<<1, 32>>>(nscan);
    k_scan3<<<nblkN, 256>>>();
    k_reorder<<<(Ee + 255) / 256, 256>>>(src, dst, ppmi);
    k_gemm1<<<nblk64, 256>>>(x, W1, b1);
    k_stats1<<<1, 64>>>();
    k_gemm2<<<nblk64, 256>>>(W2, b2, g1, be1);
    k_stats2<<<1, 32>>>();
    k_h1<<<nblk64, 256>>>(Wg1, g2, be2);
    k_conv1<<<nwarp, 256>>>(bg1);
    k_feat<<<nblk64, 256>>>(Wg2, Wg3);
    k_conv2out<<<nwarp, 256>>>(noise_p, noise_a, Watt, batt, bg2, bg3, out);
}

// round 3
// speedup vs baseline: 1.8368x; 1.1190x over previous
#include <cuda_runtime.h>
#include <cuda_fp16.h>
#include <cstdint>

#define Nn 100000
#define Ee 2400000

// ---------------- device scratch (static, no allocation) ----------------
__device__ __align__(16) float  d_tmp1[Nn * 64];   // x@W1+b1
__device__ __align__(16) float  d_tmp2[Nn * 32];   // e1@W2+b2
__device__ __align__(16) __half d_h1h[Nn * 32];    // emb@Wg1 (fp16)
__device__ __align__(16) float  d_fp[Nn * 32];     // relu(conv1 ppmi)
__device__ __align__(16) float  d_fa[Nn * 32];     // relu(conv1 gcn)
__device__ __align__(16) __half2 d_hP2[Nn * 32];   // (mu,lv) proj, ppmi side
__device__ __align__(16) __half2 d_hA2[Nn * 32];   // (mu,lv) proj, gcn side
__device__ float d_degP[Nn];
__device__ float d_degG[Nn];
__device__ int   d_cnt[Nn];
__device__ int   d_off[Nn + 1];
__device__ int   d_pos[Nn];
__device__ int   d_bsum[128];
__device__ int   d_boff[128];
__device__ __align__(16) int4 d_sedge[Ee];         // {src, np_bits, ng_bits, 0}
__device__ float d_sum1[64], d_ssq1[64];
__device__ float d_sum2[32], d_ssq2[32];
__device__ float d_mean1[64], d_rstd1[64];
__device__ float d_mean2[32], d_rstd2[32];

__device__ __forceinline__ float elu_f(float x) { return x > 0.f ? x : expm1f(x); }

__device__ __forceinline__ float warp_sum(float v) {
    #pragma unroll
    for (int o = 16; o > 0; o >>= 1) v += __shfl_xor_sync(0xffffffffu, v, o);
    return v;
}

__device__ __forceinline__ uint32_t f2tf32(float f) {
    uint32_t r;
    asm("cvt.rna.tf32.f32 %0, %1;" : "=r"(r) : "f"(f));
    return r;
}

// ---------------- init ----------------
__global__ void k_init() {
    int i = blockIdx.x * 256 + threadIdx.x;
    if (i < Nn) { d_degP[i] = 2.0f; d_degG[i] = 2.0f; d_cnt[i] = 0; }
    if (blockIdx.x == 0) {
        int t = threadIdx.x;
        if (t < 64) { d_sum1[t] = 0.f; d_ssq1[t] = 0.f; }
        else if (t < 96) { d_sum2[t - 64] = 0.f; d_ssq2[t - 64] = 0.f; }
    }
}

// ---------------- degree (over src) + dst histogram ----------------
__global__ void k_deg(const int* __restrict__ src, const int* __restrict__ dst,
                      const float* __restrict__ ppmi) {
    int e = blockIdx.x * 256 + threadIdx.x;
    if (e >= Ee) return;
    int s = src[e];
    atomicAdd(&d_degG[s], 1.0f);
    atomicAdd(&d_degP[s], ppmi[e]);
    atomicAdd(&d_cnt[dst[e]], 1);
}

__global__ void k_dinv() {
    int i = blockIdx.x * 256 + threadIdx.x;
    if (i >= Nn) return;
    d_degP[i] = rsqrtf(d_degP[i]);
    d_degG[i] = rsqrtf(d_degG[i]);
}

// ---------------- 3-step exclusive scan of d_cnt -> d_off ----------------
__global__ void k_scan1() {
    __shared__ int wsum[32];
    int b = blockIdx.x, t = threadIdx.x;
    int i = b * 1024 + t;
    int lane = t & 31, wid = t >> 5;
    int c = (i < Nn) ? d_cnt[i] : 0;
    int v = c;
    #pragma unroll
    for (int d = 1; d < 32; d <<= 1) {
        int u = __shfl_up_sync(0xffffffffu, v, d);
        if (lane >= d) v += u;
    }
    if (lane == 31) wsum[wid] = v;
    __syncthreads();
    if (wid == 0) {
        int s = wsum[lane];
        #pragma unroll
        for (int d = 1; d < 32; d <<= 1) {
            int u = __shfl_up_sync(0xffffffffu, s, d);
            if (lane >= d) s += u;
        }
        wsum[lane] = s;
    }
    __syncthreads();
    int incl = v + (wid > 0 ? wsum[wid - 1] : 0);
    if (i < Nn) d_off[i] = incl - c;
    if (t == 1023) d_bsum[b] = incl;
}

__global__ void k_scan2(int nblk) {
    if (threadIdx.x == 0) {
        int run = 0;
        for (int b = 0; b < nblk; b++) { d_boff[b] = run; run += d_bsum[b]; }
        d_off[Nn] = Ee;
    }
}

__global__ void k_scan3() {
    int i = blockIdx.x * 256 + threadIdx.x;
    if (i >= Nn) return;
    int v = d_off[i] + d_boff[i >> 10];
    d_off[i] = v;
    d_pos[i] = v;
}

// ---------------- reorder edges by dst; precompute norms; pack int4 ----------------
__global__ void k_reorder(const int* __restrict__ src, const int* __restrict__ dst,
                          const float* __restrict__ ppmi) {
    int e = blockIdx.x * 256 + threadIdx.x;
    if (e >= Ee) return;
    int s = src[e], d = dst[e];
    float w = ppmi[e];
    float np = d_degP[s] * w * d_degP[d];
    float ng = d_degG[s] * d_degG[d];
    int p = atomicAdd(&d_pos[d], 1);
    d_sedge[p] = make_int4(s, __float_as_int(np), __float_as_int(ng), 0);
}

// ---------------- GEMM1 (tf32 tensor cores): tmp1 = x@W1 + b1 ----------------
// Block: 256 thr = 8 warps; tile 128 rows x 64 cols; warp = 32x32 (2 mtiles x 4 ntiles)
__global__ void k_gemm1(const float* __restrict__ x, const float* __restrict__ W1,
                        const float* __restrict__ b1) {
    __shared__ float As[128][36];
    __shared__ float Bs[32][68];
    int t = threadIdx.x, lane = t & 31, w = t >> 5;
    int row0 = blockIdx.x * 128;
    int mb = (w & 3) * 32, nb = (w >> 2) * 32;
    float c[2][4][4] = {};
    for (int kc = 0; kc < 256; kc += 32) {
        #pragma unroll
        for (int i = 0; i < 4; i++) {
            int idx = t + i * 256;
            int r = idx >> 3, q = idx & 7;
            int gr = row0 + r;
            float4 v = (gr < Nn) ? *(const float4*)&x[gr * 256 + kc + q * 4]
                                 : make_float4(0.f, 0.f, 0.f, 0.f);
            *(float4*)&As[r][q * 4] = v;
        }
        #pragma unroll
        for (int i = 0; i < 2; i++) {
            int idx = t + i * 256;
            int k = idx >> 4, q = idx & 15;
            *(float4*)&Bs[k][q * 4] = *(const float4*)&W1[(kc + k) * 64 + q * 4];
        }
        __syncthreads();
        #pragma unroll
        for (int kt = 0; kt < 4; kt++) {
            int k0 = kt * 8;
            uint32_t a[2][4], bf[4][2];
            #pragma unroll
            for (int mt = 0; mt < 2; mt++) {
                int r = mb + mt * 16 + (lane >> 2);
                int cc = k0 + (lane & 3);
                a[mt][0] = f2tf32(As[r][cc]);
                a[mt][1] = f2tf32(As[r + 8][cc]);
                a[mt][2] = f2tf32(As[r][cc + 4]);
                a[mt][3] = f2tf32(As[r + 8][cc + 4]);
            }
            #pragma unroll
            for (int nt = 0; nt < 4; nt++) {
                int col = nb + nt * 8 + (lane >> 2);
                int kk = k0 + (lane & 3);
                bf[nt][0] = f2tf32(Bs[kk][col]);
                bf[nt][1] = f2tf32(Bs[kk + 4][col]);
            }
            #pragma unroll
            for (int mt = 0; mt < 2; mt++)
                #pragma unroll
                for (int nt = 0; nt < 4; nt++)
                    asm volatile(
                        "mma.sync.aligned.m16n8k8.row.col.f32.tf32.tf32.f32 "
                        "{%0,%1,%2,%3}, {%4,%5,%6,%7}, {%8,%9}, {%0,%1,%2,%3};"
                        : "+f"(c[mt][nt][0]), "+f"(c[mt][nt][1]),
                          "+f"(c[mt][nt][2]), "+f"(c[mt][nt][3])
                        : "r"(a[mt][0]), "r"(a[mt][1]), "r"(a[mt][2]), "r"(a[mt][3]),
                          "r"(bf[nt][0]), "r"(bf[nt][1]));
        }
        __syncthreads();
    }
    #pragma unroll
    for (int mt = 0; mt < 2; mt++) {
        int r0 = row0 + mb + mt * 16 + (lane >> 2);
        #pragma unroll
        for (int nt = 0; nt < 4; nt++) {
            int col = nb + nt * 8 + 2 * (lane & 3);
            float bv0 = b1[col], bv1 = b1[col + 1];
            if (r0 < Nn) {
                float2 v = make_float2(c[mt][nt][0] + bv0, c[mt][nt][1] + bv1);
                *(float2*)&d_tmp1[r0 * 64 + col] = v;
            }
            if (r0 + 8 < Nn) {
                float2 v = make_float2(c[mt][nt][2] + bv0, c[mt][nt][3] + bv1);
                *(float2*)&d_tmp1[(r0 + 8) * 64 + col] = v;
            }
        }
    }
}

// ---------------- stats over tmp1 ----------------
__global__ void k_stats_t1() {
    __shared__ float ss[64], sq[64];
    int t = threadIdx.x;
    int col = t & 63, rg = t >> 6;
    if (t < 64) { ss[t] = 0.f; sq[t] = 0.f; }
    __syncthreads();
    float s = 0.f, q = 0.f;
    int r0 = blockIdx.x * 1024 + rg;
    int rend = min(blockIdx.x * 1024 + 1024, Nn);
    for (int r = r0; r < rend; r += 4) {
        float v = d_tmp1[r * 64 + col];
        s += v; q += v * v;
    }
    atomicAdd(&ss[col], s);
    atomicAdd(&sq[col], q);
    __syncthreads();
    if (t < 64) { atomicAdd(&d_sum1[t], ss[t]); atomicAdd(&d_ssq1[t], sq[t]); }
}

__global__ void k_stats1() {
    int t = threadIdx.x;  // 64
    float m = d_sum1[t] / (float)Nn;
    float v = d_ssq1[t] / (float)Nn - m * m;
    d_mean1[t] = m;
    d_rstd1[t] = rsqrtf(v + 1e-3f);
}

// ---------------- GEMM2: tmp2 = elu(bn(tmp1))@W2 + b2 (+stats) ----------------
__global__ void k_gemm2(const float* __restrict__ W2, const float* __restrict__ b2,
                        const float* __restrict__ g1, const float* __restrict__ be1) {
    __shared__ float es[64][65];
    __shared__ float ws2[64][33];
    __shared__ float ssum[32], ssq[32];
    int t = threadIdx.x;
    int row0 = blockIdx.x * 64;
    #pragma unroll
    for (int i = 0; i < 16; i++) {
        int idx = t + i * 256;
        int r = idx >> 6, c = idx & 63;
        int gr = row0 + r;
        float v = (gr < Nn) ? d_tmp1[gr * 64 + c] : 0.f;
        es[r][c] = elu_f(g1[c] * (v - d_mean1[c]) * d_rstd1[c] + be1[c]);
    }
    #pragma unroll
    for (int i = 0; i < 8; i++) {
        int idx = t + i * 256;
        int k = idx >> 5, c = idx & 31;
        ws2[k][c] = W2[k * 32 + c];
    }
    if (t < 32) { ssum[t] = 0.f; ssq[t] = 0.f; }
    __syncthreads();
    int c = t & 31, r0 = t >> 5;
    float acc[8] = {};
    for (int k = 0; k < 64; k++) {
        float b = ws2[k][c];
        #pragma unroll
        for (int i = 0; i < 8; i++) acc[i] += es[r0 + 8 * i][k] * b;
    }
    #pragma unroll
    for (int i = 0; i < 8; i++) {
        int gr = row0 + r0 + 8 * i;
        if (gr < Nn) {
            float v = acc[i] + b2[c];
            d_tmp2[gr * 32 + c] = v;
            atomicAdd(&ssum[c], v);
            atomicAdd(&ssq[c], v * v);
        }
    }
    __syncthreads();
    if (t < 32) { atomicAdd(&d_sum2[t], ssum[t]); atomicAdd(&d_ssq2[t], ssq[t]); }
}

__global__ void k_stats2() {
    int t = threadIdx.x;  // 32
    float m = d_sum2[t] / (float)Nn;
    float v = d_ssq2[t] / (float)Nn - m * m;
    d_mean2[t] = m;
    d_rstd2[t] = rsqrtf(v + 1e-3f);
}

// ---------------- h1 = elu(bn(tmp2))@Wg1 -> fp16 ----------------
__global__ void k_h1(const float* __restrict__ Wg1, const float* __restrict__ g2,
                     const float* __restrict__ be2) {
    __shared__ float es[64][33];
    __shared__ float wg[32][33];
    int t = threadIdx.x;
    int row0 = blockIdx.x * 64;
    #pragma unroll
    for (int i = 0; i < 8; i++) {
        int idx = t + i * 256;
        int r = idx >> 5, c = idx & 31;
        int gr = row0 + r;
        float v = (gr < Nn) ? d_tmp2[gr * 32 + c] : 0.f;
        es[r][c] = elu_f(g2[c] * (v - d_mean2[c]) * d_rstd2[c] + be2[c]);
    }
    #pragma unroll
    for (int i = 0; i < 4; i++) {
        int idx = t + i * 256;
        wg[idx >> 5][idx & 31] = Wg1[idx];
    }
    __syncthreads();
    int c = t & 31, r0 = t >> 5;
    #pragma unroll
    for (int i = 0; i < 8; i++) {
        int r = r0 + 8 * i;
        int gr = row0 + r;
        if (gr >= Nn) continue;
        float acc = 0.f;
        #pragma unroll
        for (int k = 0; k < 32; k++) acc += es[r][k] * wg[k][c];
        d_h1h[gr * 32 + c] = __float2half_rn(acc);
    }
}

// ---------------- conv1 + fused feat projection ----------------
__global__ void k_conv1feat(const float* __restrict__ bg1,
                            const float* __restrict__ Wg2, const float* __restrict__ Wg3) {
    __shared__ float W2s[32][33], W3s[32][33];
    int t = threadIdx.x;
    for (int i = t; i < 1024; i += 256) {
        int k = i >> 5, c = i & 31;
        W2s[k][c] = Wg2[i];
        W3s[k][c] = Wg3[i];
    }
    __syncthreads();
    int gw = blockIdx.x * 8 + (t >> 5);
    int lane = t & 31;
    if (gw >= Nn) return;
    int n = gw;
    int beg = d_off[n], end = d_off[n + 1];
    float dp = d_degP[n], dg = d_degG[n];
    float self = __half2float(d_h1h[n * 32 + lane]);
    float bias = bg1[lane];
    float accp = bias + 2.f * dp * dp * self;
    float acca = bias + 2.f * dg * dg * self;
    int j = beg;
    for (; j + 4 <= end; j += 4) {
        int4 e0 = d_sedge[j], e1 = d_sedge[j + 1], e2 = d_sedge[j + 2], e3 = d_sedge[j + 3];
        float v0 = __half2float(d_h1h[e0.x * 32 + lane]);
        float v1 = __half2float(d_h1h[e1.x * 32 + lane]);
        float v2 = __half2float(d_h1h[e2.x * 32 + lane]);
        float v3 = __half2float(d_h1h[e3.x * 32 + lane]);
        accp += __int_as_float(e0.y) * v0 + __int_as_float(e1.y) * v1
              + __int_as_float(e2.y) * v2 + __int_as_float(e3.y) * v3;
        acca += __int_as_float(e0.z) * v0 + __int_as_float(e1.z) * v1
              + __int_as_float(e2.z) * v2 + __int_as_float(e3.z) * v3;
    }
    for (; j < end; j++) {
        int4 e = d_sedge[j];
        float v = __half2float(d_h1h[e.x * 32 + lane]);
        accp += __int_as_float(e.y) * v;
        acca += __int_as_float(e.z) * v;
    }
    float fpv = fmaxf(accp, 0.f);
    float fav = fmaxf(acca, 0.f);
    d_fp[n * 32 + lane] = fpv;
    d_fa[n * 32 + lane] = fav;
    // feat projection: hcat[c] = sum_k f[k] * W{2,3}[k][c], via warp broadcast
    float mup = 0.f, lvp = 0.f, mua = 0.f, lva = 0.f;
    #pragma unroll
    for (int k = 0; k < 32; k++) {
        float fk = __shfl_sync(0xffffffffu, fpv, k);
        float ak = __shfl_sync(0xffffffffu, fav, k);
        float w2 = W2s[k][lane], w3 = W3s[k][lane];
        mup += fk * w2; lvp += fk * w3;
        mua += ak * w2; lva += ak * w3;
    }
    d_hP2[n * 32 + lane] = __floats2half2_rn(mup, lvp);
    d_hA2[n * 32 + lane] = __floats2half2_rn(mua, lva);
}

// ---------------- conv2 + reparam + attention + output (fully fused) ----------------
__global__ void k_conv2out(const float* __restrict__ noise_p, const float* __restrict__ noise_a,
                           const float* __restrict__ Watt, const float* __restrict__ batt,
                           const float* __restrict__ bg2, const float* __restrict__ bg3,
                           float* __restrict__ out) {
    int gw = blockIdx.x * 8 + (threadIdx.x >> 5);
    int lane = threadIdx.x & 31;
    if (gw >= Nn) return;
    int n = gw;
    int beg = d_off[n], end = d_off[n + 1];
    float dp = d_degP[n], dg = d_degG[n];
    float sp2 = 2.f * dp * dp, sg2 = 2.f * dg * dg;
    float2 selfP = __half22float2(d_hP2[n * 32 + lane]);
    float2 selfA = __half22float2(d_hA2[n * 32 + lane]);
    float mup = bg2[lane] + sp2 * selfP.x;
    float lvp = bg3[lane] + sp2 * selfP.y;
    float mua = bg2[lane] + sg2 * selfA.x;
    float lva = bg3[lane] + sg2 * selfA.y;
    int j = beg;
    for (; j + 2 <= end; j += 2) {
        int4 e0 = d_sedge[j], e1 = d_sedge[j + 1];
        float2 p0 = __half22float2(d_hP2[e0.x * 32 + lane]);
        float2 a0 = __half22float2(d_hA2[e0.x * 32 + lane]);
        float2 p1 = __half22float2(d_hP2[e1.x * 32 + lane]);
        float2 a1 = __half22float2(d_hA2[e1.x * 32 + lane]);
        float np0 = __int_as_float(e0.y), ng0 = __int_as_float(e0.z);
        float np1 = __int_as_float(e1.y), ng1 = __int_as_float(e1.z);
        mup += np0 * p0.x + np1 * p1.x;
        lvp += np0 * p0.y + np1 * p1.y;
        mua += ng0 * a0.x + ng1 * a1.x;
        lva += ng0 * a0.y + ng1 * a1.y;
    }
    for (; j < end; j++) {
        int4 e = d_sedge[j];
        float2 p = __half22float2(d_hP2[e.x * 32 + lane]);
        float2 a = __half22float2(d_hA2[e.x * 32 + lane]);
        float np = __int_as_float(e.y), ng = __int_as_float(e.z);
        mup += np * p.x; lvp += np * p.y;
        mua += ng * a.x; lva += ng * a.y;
    }
    float fpv = d_fp[n * 32 + lane];
    float fav = d_fa[n * 32 + lane];
    float zp = noise_p[n * 32 + lane] * expf(lvp) + mup;
    float za = noise_a[n * 32 + lane] * expf(lva) + mua;
    float wv = Watt[lane];
    float b0 = batt[0];
    float la = warp_sum(fpv * wv) + b0;
    float lb = warp_sum(fav * wv) + b0;
    float lc = warp_sum(zp * wv) + b0;
    float ld = warp_sum(za * wv) + b0;
    float m1 = fmaxf(la, lb);
    float ea = expf(la - m1), eb = expf(lb - m1);
    float wa = ea / (ea + eb);
    float zf = wa * fpv + (1.f - wa) * fav;
    float m2 = fmaxf(lc, ld);
    float ec = expf(lc - m2), ed = expf(ld - m2);
    float wc = ec / (ec + ed);
    float zg = wc * zp + (1.f - wc) * za;
    out[n * 64 + lane] = zf;
    out[n * 64 + 32 + lane] = zg;
}

// ---------------- launch ----------------
extern "C" void kernel_launch(void* const* d_in, const int* in_sizes, int n_in,
                              void* d_out, int out_size) {
    const float* x       = (const float*)d_in[0];
    const int*   eidx    = (const int*)d_in[1];
    const float* ppmi    = (const float*)d_in[2];
    const float* noise_p = (const float*)d_in[3];
    const float* noise_a = (const float*)d_in[4];
    const float* W1  = (const float*)d_in[5];
    const float* b1  = (const float*)d_in[6];
    const float* g1  = (const float*)d_in[7];
    const float* be1 = (const float*)d_in[8];
    const float* W2  = (const float*)d_in[9];
    const float* b2  = (const float*)d_in[10];
    const float* g2  = (const float*)d_in[11];
    const float* be2 = (const float*)d_in[12];
    const float* Wg1 = (const float*)d_in[13];
    const float* bg1 = (const float*)d_in[14];
    const float* Wg2 = (const float*)d_in[15];
    const float* bg2 = (const float*)d_in[16];
    const float* Wg3 = (const float*)d_in[17];
    const float* bg3 = (const float*)d_in[18];
    const float* Watt = (const float*)d_in[19];
    const float* batt = (const float*)d_in[20];
    float* out = (float*)d_out;

    const int* src = eidx;        // edge_index[0]
    const int* dst = eidx + Ee;   // edge_index[1]

    int nblkN = (Nn + 255) / 256;
    int nscan = (Nn + 1023) / 1024;
    int nwarp = (Nn + 7) / 8;
    int nblk64 = (Nn + 63) / 64;
    int nblk128 = (Nn + 127) / 128;

    k_init<<<nblkN, 256>>>();
    k_deg<<<(Ee + 255) / 256, 256>>>(src, dst, ppmi);
    k_dinv<<<nblkN, 256>>>();
    k_scan1<<<nscan, 1024>>>();
    k_scan2<<<1, 32>>>(nscan);
    k_scan3<<<nblkN, 256>>>();
    k_reorder<<<(Ee + 255) / 256, 256>>>(src, dst, ppmi);
    k_gemm1<<<nblk128, 256>>>(x, W1, b1);
    k_stats_t1<<<nscan, 256>>>();
    k_stats1<<<1, 64>>>();
    k_gemm2<<<nblk64, 256>>>(W2, b2, g1, be1);
    k_stats2<<<1, 32>>>();
    k_h1<<<nblk64, 256>>>(Wg1, g2, be2);
    k_conv1feat<<<nwarp, 256>>>(bg1, Wg2, Wg3);
    k_conv2out<<<nwarp, 256>>>(noise_p, noise_a, Watt, batt, bg2, bg3, out);
}

// round 5
// speedup vs baseline: 1.9346x; 1.0532x over previous
#include <cuda_runtime.h>
#include <cuda_fp16.h>
#include <cstdint>

#define Nn 100000
#define Ee 2400000

// ---------------- device scratch (static, no allocation) ----------------
__device__ __align__(16) float  d_tmp1[Nn * 64];   // x@W1+b1
__device__ __align__(16) float  d_tmp2[Nn * 32];   // e1@W2+b2
__device__ __align__(16) __half d_h1h[Nn * 32];    // emb@Wg1 (fp16)
__device__ __align__(16) float  d_fp[Nn * 32];     // relu(conv1 ppmi)
__device__ __align__(16) float  d_fa[Nn * 32];     // relu(conv1 gcn)
__device__ __align__(16) uint2  d_hPA[Nn * 32];    // packed (muP,lvP | muA,lvA) 4xhalf
__device__ float d_degP[Nn];
__device__ float d_degG[Nn];
__device__ int   d_cnt[Nn];
__device__ int   d_off[Nn + 1];
__device__ int   d_pos[Nn];
__device__ int   d_bsum[128];
__device__ int   d_boff[128];
__device__ __align__(16) int4 d_sedge[Ee];         // {src, np_bits, ng_bits, 0}
__device__ float d_sum1[64], d_ssq1[64];
__device__ float d_sum2[32], d_ssq2[32];

__device__ __forceinline__ float elu_f(float x) { return x > 0.f ? x : expm1f(x); }

__device__ __forceinline__ float warp_sum(float v) {
    #pragma unroll
    for (int o = 16; o > 0; o >>= 1) v += __shfl_xor_sync(0xffffffffu, v, o);
    return v;
}

__device__ __forceinline__ uint32_t f2tf32(float f) {
    uint32_t r;
    asm("cvt.rna.tf32.f32 %0, %1;" : "=r"(r) : "f"(f));
    return r;
}

// ---------------- init ----------------
__global__ void k_init() {
    int i = blockIdx.x * 256 + threadIdx.x;
    if (i < Nn) { d_degP[i] = 2.0f; d_degG[i] = 2.0f; d_cnt[i] = 0; }
    if (blockIdx.x == 0) {
        int t = threadIdx.x;
        if (t < 64) { d_sum1[t] = 0.f; d_ssq1[t] = 0.f; }
        else if (t < 96) { d_sum2[t - 64] = 0.f; d_ssq2[t - 64] = 0.f; }
    }
}

// ---------------- degree (over src) + dst histogram ----------------
__global__ void k_deg(const int* __restrict__ src, const int* __restrict__ dst,
                      const float* __restrict__ ppmi) {
    int e = blockIdx.x * 256 + threadIdx.x;
    if (e >= Ee) return;
    int s = __ldg(&src[e]);
    atomicAdd(&d_degG[s], 1.0f);
    atomicAdd(&d_degP[s], __ldg(&ppmi[e]));
    atomicAdd(&d_cnt[__ldg(&dst[e])], 1);
}

// ---------------- scan block-partials + dinv (merged) ----------------
__global__ void k_scan1() {
    __shared__ int wsum[32];
    int b = blockIdx.x, t = threadIdx.x;
    int i = b * 1024 + t;
    int lane = t & 31, wid = t >> 5;
    if (i < Nn) {                       // fused dinv
        d_degP[i] = rsqrtf(d_degP[i]);
        d_degG[i] = rsqrtf(d_degG[i]);
    }
    int c = (i < Nn) ? d_cnt[i] : 0;
    int v = c;
    #pragma unroll
    for (int d = 1; d < 32; d <<= 1) {
        int u = __shfl_up_sync(0xffffffffu, v, d);
        if (lane >= d) v += u;
    }
    if (lane == 31) wsum[wid] = v;
    __syncthreads();
    if (wid == 0) {
        int s = wsum[lane];
        #pragma unroll
        for (int d = 1; d < 32; d <<= 1) {
            int u = __shfl_up_sync(0xffffffffu, s, d);
            if (lane >= d) s += u;
        }
        wsum[lane] = s;
    }
    __syncthreads();
    int incl = v + (wid > 0 ? wsum[wid - 1] : 0);
    if (i < Nn) d_off[i] = incl - c;
    if (t == 1023) d_bsum[b] = incl;
}

// warp-scan over <=128 block partials (4 chunks of 32, serial carry)
__global__ void k_scan2(int nblk) {
    int lane = threadIdx.x;  // 32 threads
    int carry = 0;
    for (int base = 0; base < nblk; base += 32) {
        int i = base + lane;
        int v = (i < nblk) ? d_bsum[i] : 0;
        int s = v;
        #pragma unroll
        for (int d = 1; d < 32; d <<= 1) {
            int u = __shfl_up_sync(0xffffffffu, s, d);
            if (lane >= d) s += u;
        }
        if (i < nblk) d_boff[i] = carry + s - v;   // exclusive
        carry += __shfl_sync(0xffffffffu, s, 31);
    }
    if (lane == 0) d_off[Nn] = Ee;
}

__global__ void k_scan3() {
    int i = blockIdx.x * 256 + threadIdx.x;
    if (i >= Nn) return;
    int v = d_off[i] + d_boff[i >> 10];
    d_off[i] = v;
    d_pos[i] = v;
}

// ---------------- reorder edges by dst; precompute norms; pack int4 ----------------
__global__ void k_reorder(const int* __restrict__ src, const int* __restrict__ dst,
                          const float* __restrict__ ppmi) {
    int e = blockIdx.x * 256 + threadIdx.x;
    if (e >= Ee) return;
    int s = __ldg(&src[e]), d = __ldg(&dst[e]);
    float w = __ldg(&ppmi[e]);
    float np = d_degP[s] * w * d_degP[d];
    float ng = d_degG[s] * d_degG[d];
    int p = atomicAdd(&d_pos[d], 1);
    d_sedge[p] = make_int4(s, __float_as_int(np), __float_as_int(ng), 0);
}

// ---------------- GEMM1 (tf32 mma) + fused BN stats ----------------
__global__ void __launch_bounds__(256) k_gemm1(const float* __restrict__ x,
                                               const float* __restrict__ W1,
                                               const float* __restrict__ b1) {
    __shared__ float As[128][36];
    __shared__ float Bs[32][68];
    int t = threadIdx.x, lane = t & 31, w = t >> 5;
    int row0 = blockIdx.x * 128;
    int mb = (w & 3) * 32, nb = (w >> 2) * 32;
    float c[2][4][4] = {};
    for (int kc = 0; kc < 256; kc += 32) {
        #pragma unroll
        for (int i = 0; i < 4; i++) {
            int idx = t + i * 256;
            int r = idx >> 3, q = idx & 7;
            int gr = row0 + r;
            float4 v = (gr < Nn) ? *(const float4*)&x[gr * 256 + kc + q * 4]
                                 : make_float4(0.f, 0.f, 0.f, 0.f);
            *(float4*)&As[r][q * 4] = v;
        }
        #pragma unroll
        for (int i = 0; i < 2; i++) {
            int idx = t + i * 256;
            int k = idx >> 4, q = idx & 15;
            *(float4*)&Bs[k][q * 4] = *(const float4*)&W1[(kc + k) * 64 + q * 4];
        }
        __syncthreads();
        #pragma unroll
        for (int kt = 0; kt < 4; kt++) {
            int k0 = kt * 8;
            uint32_t a[2][4], bf[4][2];
            #pragma unroll
            for (int mt = 0; mt < 2; mt++) {
                int r = mb + mt * 16 + (lane >> 2);
                int cc = k0 + (lane & 3);
                a[mt][0] = f2tf32(As[r][cc]);
                a[mt][1] = f2tf32(As[r + 8][cc]);
                a[mt][2] = f2tf32(As[r][cc + 4]);
                a[mt][3] = f2tf32(As[r + 8][cc + 4]);
            }
            #pragma unroll
            for (int nt = 0; nt < 4; nt++) {
                int col = nb + nt * 8 + (lane >> 2);
                int kk = k0 + (lane & 3);
                bf[nt][0] = f2tf32(Bs[kk][col]);
                bf[nt][1] = f2tf32(Bs[kk + 4][col]);
            }
            #pragma unroll
            for (int mt = 0; mt < 2; mt++)
                #pragma unroll
                for (int nt = 0; nt < 4; nt++)
                    asm volatile(
                        "mma.sync.aligned.m16n8k8.row.col.f32.tf32.tf32.f32 "
                        "{%0,%1,%2,%3}, {%4,%5,%6,%7}, {%8,%9}, {%0,%1,%2,%3};"
                        : "+f"(c[mt][nt][0]), "+f"(c[mt][nt][1]),
                          "+f"(c[mt][nt][2]), "+f"(c[mt][nt][3])
                        : "r"(a[mt][0]), "r"(a[mt][1]), "r"(a[mt][2]), "r"(a[mt][3]),
                          "r"(bf[nt][0]), "r"(bf[nt][1]));
        }
        __syncthreads();
    }
    float s0[4] = {}, q0[4] = {}, s1[4] = {}, q1[4] = {};
    #pragma unroll
    for (int mt = 0; mt < 2; mt++) {
        int r0 = row0 + mb + mt * 16 + (lane >> 2);
        bool ok0 = r0 < Nn, ok1 = (r0 + 8) < Nn;
        #pragma unroll
        for (int nt = 0; nt < 4; nt++) {
            int col = nb + nt * 8 + 2 * (lane & 3);
            float bv0 = b1[col], bv1 = b1[col + 1];
            float x0 = c[mt][nt][0] + bv0, x1 = c[mt][nt][1] + bv1;
            float y0 = c[mt][nt][2] + bv0, y1 = c[mt][nt][3] + bv1;
            if (ok0) *(float2*)&d_tmp1[r0 * 64 + col] = make_float2(x0, x1);
            if (ok1) *(float2*)&d_tmp1[(r0 + 8) * 64 + col] = make_float2(y0, y1);
            if (ok0) { s0[nt] += x0; q0[nt] += x0 * x0; s1[nt] += x1; q1[nt] += x1 * x1; }
            if (ok1) { s0[nt] += y0; q0[nt] += y0 * y0; s1[nt] += y1; q1[nt] += y1 * y1; }
        }
    }
    #pragma unroll
    for (int nt = 0; nt < 4; nt++) {
        #pragma unroll
        for (int o = 16; o >= 4; o >>= 1) {
            s0[nt] += __shfl_xor_sync(0xffffffffu, s0[nt], o);
            q0[nt] += __shfl_xor_sync(0xffffffffu, q0[nt], o);
            s1[nt] += __shfl_xor_sync(0xffffffffu, s1[nt], o);
            q1[nt] += __shfl_xor_sync(0xffffffffu, q1[nt], o);
        }
        if ((lane >> 2) == 0) {
            int col = nb + nt * 8 + 2 * (lane & 3);
            atomicAdd(&d_sum1[col], s0[nt]);
            atomicAdd(&d_ssq1[col], q0[nt]);
            atomicAdd(&d_sum1[col + 1], s1[nt]);
            atomicAdd(&d_ssq1[col + 1], q1[nt]);
        }
    }
}

// ---------------- GEMM2: tmp2 = elu(bn(tmp1))@W2 + b2 (stats inline + out-stats) ----------------
__global__ void __launch_bounds__(256) k_gemm2(const float* __restrict__ W2,
                                               const float* __restrict__ b2,
                                               const float* __restrict__ g1,
                                               const float* __restrict__ be1) {
    __shared__ float es[64][65];
    __shared__ float ws2[64][33];
    __shared__ float ssum[32], ssq[32];
    __shared__ float m1s[64], r1s[64];
    int t = threadIdx.x;
    int row0 = blockIdx.x * 64;
    if (t < 64) {
        float m = d_sum1[t] * (1.0f / (float)Nn);
        float v = d_ssq1[t] * (1.0f / (float)Nn) - m * m;
        m1s[t] = m;
        r1s[t] = rsqrtf(v + 1e-3f);
    }
    if (t >= 224) { int u = t - 224; ssum[u] = 0.f; ssq[u] = 0.f; }
    __syncthreads();
    #pragma unroll
    for (int i = 0; i < 16; i++) {
        int idx = t + i * 256;
        int r = idx >> 6, c = idx & 63;
        int gr = row0 + r;
        float v = (gr < Nn) ? d_tmp1[gr * 64 + c] : 0.f;
        es[r][c] = elu_f(g1[c] * (v - m1s[c]) * r1s[c] + be1[c]);
    }
    #pragma unroll
    for (int i = 0; i < 8; i++) {
        int idx = t + i * 256;
        int k = idx >> 5, c = idx & 31;
        ws2[k][c] = W2[k * 32 + c];
    }
    __syncthreads();
    int c = t & 31, r0 = t >> 5;
    float acc[8] = {};
    for (int k = 0; k < 64; k++) {
        float b = ws2[k][c];
        #pragma unroll
        for (int i = 0; i < 8; i++) acc[i] += es[r0 + 8 * i][k] * b;
    }
    float bv = b2[c];
    #pragma unroll
    for (int i = 0; i < 8; i++) {
        int gr = row0 + r0 + 8 * i;
        if (gr < Nn) {
            float v = acc[i] + bv;
            d_tmp2[gr * 32 + c] = v;
            atomicAdd(&ssum[c], v);
            atomicAdd(&ssq[c], v * v);
        }
    }
    __syncthreads();
    if (t < 32) { atomicAdd(&d_sum2[t], ssum[t]); atomicAdd(&d_ssq2[t], ssq[t]); }
}

// ---------------- h1 = elu(bn(tmp2))@Wg1 -> fp16  (stats2 inline) ----------------
__global__ void __launch_bounds__(256) k_h1(const float* __restrict__ Wg1,
                                            const float* __restrict__ g2,
                                            const float* __restrict__ be2) {
    __shared__ float es[64][33];
    __shared__ float wg[32][33];
    __shared__ float m2s[32], r2s[32];
    int t = threadIdx.x;
    int row0 = blockIdx.x * 64;
    if (t < 32) {
        float m = d_sum2[t] * (1.0f / (float)Nn);
        float v = d_ssq2[t] * (1.0f / (float)Nn) - m * m;
        m2s[t] = m;
        r2s[t] = rsqrtf(v + 1e-3f);
    }
    __syncthreads();
    #pragma unroll
    for (int i = 0; i < 8; i++) {
        int idx = t + i * 256;
        int r = idx >> 5, c = idx & 31;
        int gr = row0 + r;
        float v = (gr < Nn) ? d_tmp2[gr * 32 + c] : 0.f;
        es[r][c] = elu_f(g2[c] * (v - m2s[c]) * r2s[c] + be2[c]);
    }
    #pragma unroll
    for (int i = 0; i < 4; i++) {
        int idx = t + i * 256;
        wg[idx >> 5][idx & 31] = Wg1[idx];
    }
    __syncthreads();
    int c = t & 31, r0 = t >> 5;
    #pragma unroll
    for (int i = 0; i < 8; i++) {
        int r = r0 + 8 * i;
        int gr = row0 + r;
        if (gr >= Nn) continue;
        float acc = 0.f;
        #pragma unroll
        for (int k = 0; k < 32; k++) acc += es[r][k] * wg[k][c];
        d_h1h[gr * 32 + c] = __float2half_rn(acc);
    }
}

// ---------------- conv1 + fused feat projection -> packed d_hPA ----------------
__global__ void __launch_bounds__(256) k_conv1feat(const float* __restrict__ bg1,
                                                   const float* __restrict__ Wg2,
                                                   const float* __restrict__ Wg3) {
    __shared__ float W2s[32][33], W3s[32][33];
    int t = threadIdx.x;
    for (int i = t; i < 1024; i += 256) {
        int k = i >> 5, c = i & 31;
        W2s[k][c] = Wg2[i];
        W3s[k][c] = Wg3[i];
    }
    __syncthreads();
    int gw = blockIdx.x * 8 + (t >> 5);
    int lane = t & 31;
    if (gw >= Nn) return;
    int n = gw;
    int beg = d_off[n], end = d_off[n + 1];
    float dp = d_degP[n], dg = d_degG[n];
    float self = __half2float(d_h1h[n * 32 + lane]);
    float bias = bg1[lane];
    float accp = bias + 2.f * dp * dp * self;
    float acca = bias + 2.f * dg * dg * self;
    int j = beg;
    for (; j + 4 <= end; j += 4) {
        int4 e0 = __ldg(&d_sedge[j]);
        int4 e1 = __ldg(&d_sedge[j + 1]);
        int4 e2 = __ldg(&d_sedge[j + 2]);
        int4 e3 = __ldg(&d_sedge[j + 3]);
        float v0 = __half2float(__ldg(&d_h1h[e0.x * 32 + lane]));
        float v1 = __half2float(__ldg(&d_h1h[e1.x * 32 + lane]));
        float v2 = __half2float(__ldg(&d_h1h[e2.x * 32 + lane]));
        float v3 = __half2float(__ldg(&d_h1h[e3.x * 32 + lane]));
        accp += __int_as_float(e0.y) * v0 + __int_as_float(e1.y) * v1
              + __int_as_float(e2.y) * v2 + __int_as_float(e3.y) * v3;
        acca += __int_as_float(e0.z) * v0 + __int_as_float(e1.z) * v1
              + __int_as_float(e2.z) * v2 + __int_as_float(e3.z) * v3;
    }
    for (; j < end; j++) {
        int4 e = __ldg(&d_sedge[j]);
        float v = __half2float(__ldg(&d_h1h[e.x * 32 + lane]));
        accp += __int_as_float(e.y) * v;
        acca += __int_as_float(e.z) * v;
    }
    float fpv = fmaxf(accp, 0.f);
    float fav = fmaxf(acca, 0.f);
    d_fp[n * 32 + lane] = fpv;
    d_fa[n * 32 + lane] = fav;
    float mup = 0.f, lvp = 0.f, mua = 0.f, lva = 0.f;
    #pragma unroll
    for (int k = 0; k < 32; k++) {
        float fk = __shfl_sync(0xffffffffu, fpv, k);
        float ak = __shfl_sync(0xffffffffu, fav, k);
        float w2 = W2s[k][lane], w3 = W3s[k][lane];
        mup += fk * w2; lvp += fk * w3;
        mua += ak * w2; lva += ak * w3;
    }
    __half2 hp = __floats2half2_rn(mup, lvp);
    __half2 ha = __floats2half2_rn(mua, lva);
    uint2 pk;
    pk.x = *(uint32_t*)&hp;
    pk.y = *(uint32_t*)&ha;
    d_hPA[n * 32 + lane] = pk;
}

// ---------------- conv2 + reparam + attention + output (single gather) ----------------
__global__ void __launch_bounds__(256) k_conv2out(const float* __restrict__ noise_p,
                                                  const float* __restrict__ noise_a,
                                                  const float* __restrict__ Watt,
                                                  const float* __restrict__ batt,
                                                  const float* __restrict__ bg2,
                                                  const float* __restrict__ bg3,
                                                  float* __restrict__ out) {
    int gw = blockIdx.x * 8 + (threadIdx.x >> 5);
    int lane = threadIdx.x & 31;
    if (gw >= Nn) return;
    int n = gw;
    int beg = d_off[n], end = d_off[n + 1];
    float dp = d_degP[n], dg = d_degG[n];
    float sp2 = 2.f * dp * dp, sg2 = 2.f * dg * dg;
    uint2 selfpk = d_hPA[n * 32 + lane];
    float2 selfP = __half22float2(*(__half2*)&selfpk.x);
    float2 selfA = __half22float2(*(__half2*)&selfpk.y);
    float mup = bg2[lane] + sp2 * selfP.x;
    float lvp = bg3[lane] + sp2 * selfP.y;
    float mua = bg2[lane] + sg2 * selfA.x;
    float lva = bg3[lane] + sg2 * selfA.y;
    int j = beg;
    for (; j + 4 <= end; j += 4) {
        int4 e0 = __ldg(&d_sedge[j]);
        int4 e1 = __ldg(&d_sedge[j + 1]);
        int4 e2 = __ldg(&d_sedge[j + 2]);
        int4 e3 = __ldg(&d_sedge[j + 3]);
        uint2 g0 = __ldg(&d_hPA[e0.x * 32 + lane]);
        uint2 g1 = __ldg(&d_hPA[e1.x * 32 + lane]);
        uint2 g2 = __ldg(&d_hPA[e2.x * 32 + lane]);
        uint2 g3 = __ldg(&d_hPA[e3.x * 32 + lane]);
        float2 p0 = __half22float2(*(__half2*)&g0.x), a0 = __half22float2(*(__half2*)&g0.y);
        float2 p1 = __half22float2(*(__half2*)&g1.x), a1 = __half22float2(*(__half2*)&g1.y);
        float2 p2 = __half22float2(*(__half2*)&g2.x), a2 = __half22float2(*(__half2*)&g2.y);
        float2 p3 = __half22float2(*(__half2*)&g3.x), a3 = __half22float2(*(__half2*)&g3.y);
        float np0 = __int_as_float(e0.y), ng0 = __int_as_float(e0.z);
        float np1 = __int_as_float(e1.y), ng1 = __int_as_float(e1.z);
        float np2 = __int_as_float(e2.y), ng2 = __int_as_float(e2.z);
        float np3 = __int_as_float(e3.y), ng3 = __int_as_float(e3.z);
        mup += np0 * p0.x + np1 * p1.x + np2 * p2.x + np3 * p3.x;
        lvp += np0 * p0.y + np1 * p1.y + np2 * p2.y + np3 * p3.y;
        mua += ng0 * a0.x + ng1 * a1.x + ng2 * a2.x + ng3 * a3.x;
        lva += ng0 * a0.y + ng1 * a1.y + ng2 * a2.y + ng3 * a3.y;
    }
    for (; j < end; j++) {
        int4 e = __ldg(&d_sedge[j]);
        uint2 g = __ldg(&d_hPA[e.x * 32 + lane]);
        float2 p = __half22float2(*(__half2*)&g.x);
        float2 a = __half22float2(*(__half2*)&g.y);
        float np = __int_as_float(e.y), ng = __int_as_float(e.z);
        mup += np * p.x; lvp += np * p.y;
        mua += ng * a.x; lva += ng * a.y;
    }
    float fpv = d_fp[n * 32 + lane];
    float fav = d_fa[n * 32 + lane];
    float zp = noise_p[n * 32 + lane] * expf(lvp) + mup;
    float za = noise_a[n * 32 + lane] * expf(lva) + mua;
    float wv = Watt[lane];
    float b0 = batt[0];
    float la = warp_sum(fpv * wv) + b0;
    float lb = warp_sum(fav * wv) + b0;
    float lc = warp_sum(zp * wv) + b0;
    float ld = warp_sum(za * wv) + b0;
    float m1 = fmaxf(la, lb);
    float ea = expf(la - m1), eb = expf(lb - m1);
    float wa = ea / (ea + eb);
    float zf = wa * fpv + (1.f - wa) * fav;
    float m2 = fmaxf(lc, ld);
    float ec = expf(lc - m2), ed = expf(ld - m2);
    float wc = ec / (ec + ed);
    float zg = wc * zp + (1.f - wc) * za;
    out[n * 64 + lane] = zf;
    out[n * 64 + 32 + lane] = zg;
}

// ---------------- launch ----------------
extern "C" void kernel_launch(void* const* d_in, const int* in_sizes, int n_in,
                              void* d_out, int out_size) {
    const float* x       = (const float*)d_in[0];
    const int*   eidx    = (const int*)d_in[1];
    const float* ppmi    = (const float*)d_in[2];
    const float* noise_p = (const float*)d_in[3];
    const float* noise_a = (const float*)d_in[4];
    const float* W1  = (const float*)d_in[5];
    const float* b1  = (const float*)d_in[6];
    const float* g1  = (const float*)d_in[7];
    const float* be1 = (const float*)d_in[8];
    const float* W2  = (const float*)d_in[9];
    const float* b2  = (const float*)d_in[10];
    const float* g2  = (const float*)d_in[11];
    const float* be2 = (const float*)d_in[12];
    const float* Wg1 = (const float*)d_in[13];
    const float* bg1 = (const float*)d_in[14];
    const float* Wg2 = (const float*)d_in[15];
    const float* bg2 = (const float*)d_in[16];
    const float* Wg3 = (const float*)d_in[17];
    const float* bg3 = (const float*)d_in[18];
    const float* Watt = (const float*)d_in[19];
    const float* batt = (const float*)d_in[20];
    float* out = (float*)d_out;

    const int* src = eidx;
    const int* dst = eidx + Ee;

    int nblkN = (Nn + 255) / 256;
    int nscan = (Nn + 1023) / 1024;
    int nwarp = (Nn + 7) / 8;
    int nblk64 = (Nn + 63) / 64;
    int nblk128 = (Nn + 127) / 128;

    k_init<<<nblkN, 256>>>();
    k_deg<<<(Ee + 255) / 256, 256>>>(src, dst, ppmi);
    k_scan1<<<nscan, 1024>>>();
    k_scan2<<<1, 32>>>(nscan);
    k_scan3<<<nblkN, 256>>>();
    k_reorder<<<(Ee + 255) / 256, 256>>>(src, dst, ppmi);
    k_gemm1<<<nblk128, 256>>>(x, W1, b1);
    k_gemm2<<<nblk64, 256>>>(W2, b2, g1, be1);
    k_h1<<<nblk64, 256>>>(Wg1, g2, be2);
    k_conv1feat<<<nwarp, 256>>>(bg1, Wg2, Wg3);
    k_conv2out<<<nwarp, 256>>>(noise_p, noise_a, Watt, batt, bg2, bg3, out);
}

// round 6
// speedup vs baseline: 2.0301x; 1.0494x over previous
#include <cuda_runtime.h>
#include <cuda_fp16.h>
#include <cstdint>

#define Nn 100000
#define Ee 2400000

// ---------------- device scratch (static, no allocation) ----------------
__device__ __align__(16) float  d_tmp1[Nn * 64];   // x@W1+b1
__device__ __align__(16) float  d_tmp2[Nn * 32];   // e1@W2+b2
__device__ __align__(16) __half d_h1h[Nn * 32];    // emb@Wg1 (fp16)
__device__ __align__(16) float  d_fp[Nn * 32];     // relu(conv1 ppmi) fp32
__device__ __align__(16) float  d_fa[Nn * 32];     // relu(conv1 gcn)  fp32
__device__ __align__(16) uint32_t d_fpfa[Nn * 32]; // packed half2 (fp, fa) for gathers
__device__ float d_degP[Nn];
__device__ float d_degG[Nn];
__device__ int   d_cnt[Nn];
__device__ int   d_off[Nn + 1];
__device__ int   d_pos[Nn];
__device__ int   d_bsum[128];
__device__ int   d_boff[128];
__device__ __align__(16) int4 d_sedge[Ee];         // {src, np_bits, ng_bits, 0}
__device__ float d_sum1[64], d_ssq1[64];
__device__ float d_sum2[32], d_ssq2[32];

__device__ __forceinline__ float elu_f(float x) { return x > 0.f ? x : expm1f(x); }

__device__ __forceinline__ float warp_sum(float v) {
    #pragma unroll
    for (int o = 16; o > 0; o >>= 1) v += __shfl_xor_sync(0xffffffffu, v, o);
    return v;
}

__device__ __forceinline__ uint32_t f2tf32(float f) {
    uint32_t r;
    asm("cvt.rna.tf32.f32 %0, %1;" : "=r"(r) : "f"(f));
    return r;
}

// ---------------- init ----------------
__global__ void k_init() {
    int i = blockIdx.x * 256 + threadIdx.x;
    if (i < Nn) { d_degP[i] = 2.0f; d_degG[i] = 2.0f; d_cnt[i] = 0; }
    if (blockIdx.x == 0) {
        int t = threadIdx.x;
        if (t < 64) { d_sum1[t] = 0.f; d_ssq1[t] = 0.f; }
        else if (t < 96) { d_sum2[t - 64] = 0.f; d_ssq2[t - 64] = 0.f; }
    }
}

// ---------------- degree (over src) + dst histogram ----------------
__global__ void k_deg(const int* __restrict__ src, const int* __restrict__ dst,
                      const float* __restrict__ ppmi) {
    int e = blockIdx.x * 256 + threadIdx.x;
    if (e >= Ee) return;
    int s = __ldg(&src[e]);
    atomicAdd(&d_degG[s], 1.0f);
    atomicAdd(&d_degP[s], __ldg(&ppmi[e]));
    atomicAdd(&d_cnt[__ldg(&dst[e])], 1);
}

// ---------------- scan block-partials + dinv (merged) ----------------
__global__ void k_scan1() {
    __shared__ int wsum[32];
    int b = blockIdx.x, t = threadIdx.x;
    int i = b * 1024 + t;
    int lane = t & 31, wid = t >> 5;
    if (i < Nn) {
        d_degP[i] = rsqrtf(d_degP[i]);
        d_degG[i] = rsqrtf(d_degG[i]);
    }
    int c = (i < Nn) ? d_cnt[i] : 0;
    int v = c;
    #pragma unroll
    for (int d = 1; d < 32; d <<= 1) {
        int u = __shfl_up_sync(0xffffffffu, v, d);
        if (lane >= d) v += u;
    }
    if (lane == 31) wsum[wid] = v;
    __syncthreads();
    if (wid == 0) {
        int s = wsum[lane];
        #pragma unroll
        for (int d = 1; d < 32; d <<= 1) {
            int u = __shfl_up_sync(0xffffffffu, s, d);
            if (lane >= d) s += u;
        }
        wsum[lane] = s;
    }
    __syncthreads();
    int incl = v + (wid > 0 ? wsum[wid - 1] : 0);
    if (i < Nn) d_off[i] = incl - c;
    if (t == 1023) d_bsum[b] = incl;
}

__global__ void k_scan2(int nblk) {
    int lane = threadIdx.x;  // 32 threads
    int carry = 0;
    for (int base = 0; base < nblk; base += 32) {
        int i = base + lane;
        int v = (i < nblk) ? d_bsum[i] : 0;
        int s = v;
        #pragma unroll
        for (int d = 1; d < 32; d <<= 1) {
            int u = __shfl_up_sync(0xffffffffu, s, d);
            if (lane >= d) s += u;
        }
        if (i < nblk) d_boff[i] = carry + s - v;
        carry += __shfl_sync(0xffffffffu, s, 31);
    }
    if (lane == 0) d_off[Nn] = Ee;
}

__global__ void k_scan3() {
    int i = blockIdx.x * 256 + threadIdx.x;
    if (i >= Nn) return;
    int v = d_off[i] + d_boff[i >> 10];
    d_off[i] = v;
    d_pos[i] = v;
}

// ---------------- reorder edges by dst; precompute norms; pack int4 ----------------
__global__ void k_reorder(const int* __restrict__ src, const int* __restrict__ dst,
                          const float* __restrict__ ppmi) {
    int e = blockIdx.x * 256 + threadIdx.x;
    if (e >= Ee) return;
    int s = __ldg(&src[e]), d = __ldg(&dst[e]);
    float w = __ldg(&ppmi[e]);
    float np = d_degP[s] * w * d_degP[d];
    float ng = d_degG[s] * d_degG[d];
    int p = atomicAdd(&d_pos[d], 1);
    d_sedge[p] = make_int4(s, __float_as_int(np), __float_as_int(ng), 0);
}

// ---------------- GEMM1 (tf32 mma) + fused BN stats ----------------
__global__ void __launch_bounds__(256) k_gemm1(const float* __restrict__ x,
                                               const float* __restrict__ W1,
                                               const float* __restrict__ b1) {
    __shared__ float As[128][36];
    __shared__ float Bs[32][68];
    int t = threadIdx.x, lane = t & 31, w = t >> 5;
    int row0 = blockIdx.x * 128;
    int mb = (w & 3) * 32, nb = (w >> 2) * 32;
    float c[2][4][4] = {};
    for (int kc = 0; kc < 256; kc += 32) {
        #pragma unroll
        for (int i = 0; i < 4; i++) {
            int idx = t + i * 256;
            int r = idx >> 3, q = idx & 7;
            int gr = row0 + r;
            float4 v = (gr < Nn) ? *(const float4*)&x[gr * 256 + kc + q * 4]
                                 : make_float4(0.f, 0.f, 0.f, 0.f);
            *(float4*)&As[r][q * 4] = v;
        }
        #pragma unroll
        for (int i = 0; i < 2; i++) {
            int idx = t + i * 256;
            int k = idx >> 4, q = idx & 15;
            *(float4*)&Bs[k][q * 4] = *(const float4*)&W1[(kc + k) * 64 + q * 4];
        }
        __syncthreads();
        #pragma unroll
        for (int kt = 0; kt < 4; kt++) {
            int k0 = kt * 8;
            uint32_t a[2][4], bf[4][2];
            #pragma unroll
            for (int mt = 0; mt < 2; mt++) {
                int r = mb + mt * 16 + (lane >> 2);
                int cc = k0 + (lane & 3);
                a[mt][0] = f2tf32(As[r][cc]);
                a[mt][1] = f2tf32(As[r + 8][cc]);
                a[mt][2] = f2tf32(As[r][cc + 4]);
                a[mt][3] = f2tf32(As[r + 8][cc + 4]);
            }
            #pragma unroll
            for (int nt = 0; nt < 4; nt++) {
                int col = nb + nt * 8 + (lane >> 2);
                int kk = k0 + (lane & 3);
                bf[nt][0] = f2tf32(Bs[kk][col]);
                bf[nt][1] = f2tf32(Bs[kk + 4][col]);
            }
            #pragma unroll
            for (int mt = 0; mt < 2; mt++)
                #pragma unroll
                for (int nt = 0; nt < 4; nt++)
                    asm volatile(
                        "mma.sync.aligned.m16n8k8.row.col.f32.tf32.tf32.f32 "
                        "{%0,%1,%2,%3}, {%4,%5,%6,%7}, {%8,%9}, {%0,%1,%2,%3};"
                        : "+f"(c[mt][nt][0]), "+f"(c[mt][nt][1]),
                          "+f"(c[mt][nt][2]), "+f"(c[mt][nt][3])
                        : "r"(a[mt][0]), "r"(a[mt][1]), "r"(a[mt][2]), "r"(a[mt][3]),
                          "r"(bf[nt][0]), "r"(bf[nt][1]));
        }
        __syncthreads();
    }
    float s0[4] = {}, q0[4] = {}, s1[4] = {}, q1[4] = {};
    #pragma unroll
    for (int mt = 0; mt < 2; mt++) {
        int r0 = row0 + mb + mt * 16 + (lane >> 2);
        bool ok0 = r0 < Nn, ok1 = (r0 + 8) < Nn;
        #pragma unroll
        for (int nt = 0; nt < 4; nt++) {
            int col = nb + nt * 8 + 2 * (lane & 3);
            float bv0 = b1[col], bv1 = b1[col + 1];
            float x0 = c[mt][nt][0] + bv0, x1 = c[mt][nt][1] + bv1;
            float y0 = c[mt][nt][2] + bv0, y1 = c[mt][nt][3] + bv1;
            if (ok0) *(float2*)&d_tmp1[r0 * 64 + col] = make_float2(x0, x1);
            if (ok1) *(float2*)&d_tmp1[(r0 + 8) * 64 + col] = make_float2(y0, y1);
            if (ok0) { s0[nt] += x0; q0[nt] += x0 * x0; s1[nt] += x1; q1[nt] += x1 * x1; }
            if (ok1) { s0[nt] += y0; q0[nt] += y0 * y0; s1[nt] += y1; q1[nt] += y1 * y1; }
        }
    }
    #pragma unroll
    for (int nt = 0; nt < 4; nt++) {
        #pragma unroll
        for (int o = 16; o >= 4; o >>= 1) {
            s0[nt] += __shfl_xor_sync(0xffffffffu, s0[nt], o);
            q0[nt] += __shfl_xor_sync(0xffffffffu, q0[nt], o);
            s1[nt] += __shfl_xor_sync(0xffffffffu, s1[nt], o);
            q1[nt] += __shfl_xor_sync(0xffffffffu, q1[nt], o);
        }
        if ((lane >> 2) == 0) {
            int col = nb + nt * 8 + 2 * (lane & 3);
            atomicAdd(&d_sum1[col], s0[nt]);
            atomicAdd(&d_ssq1[col], q0[nt]);
            atomicAdd(&d_sum1[col + 1], s1[nt]);
            atomicAdd(&d_ssq1[col + 1], q1[nt]);
        }
    }
}

// ---------------- GEMM2: tmp2 = elu(bn(tmp1))@W2 + b2 (stats inline + out-stats) ----------------
__global__ void __launch_bounds__(256) k_gemm2(const float* __restrict__ W2,
                                               const float* __restrict__ b2,
                                               const float* __restrict__ g1,
                                               const float* __restrict__ be1) {
    __shared__ float es[64][65];
    __shared__ float ws2[64][33];
    __shared__ float ssum[32], ssq[32];
    __shared__ float m1s[64], r1s[64];
    int t = threadIdx.x;
    int row0 = blockIdx.x * 64;
    if (t < 64) {
        float m = d_sum1[t] * (1.0f / (float)Nn);
        float v = d_ssq1[t] * (1.0f / (float)Nn) - m * m;
        m1s[t] = m;
        r1s[t] = rsqrtf(v + 1e-3f);
    }
    if (t >= 224) { int u = t - 224; ssum[u] = 0.f; ssq[u] = 0.f; }
    __syncthreads();
    #pragma unroll
    for (int i = 0; i < 16; i++) {
        int idx = t + i * 256;
        int r = idx >> 6, c = idx & 63;
        int gr = row0 + r;
        float v = (gr < Nn) ? d_tmp1[gr * 64 + c] : 0.f;
        es[r][c] = elu_f(g1[c] * (v - m1s[c]) * r1s[c] + be1[c]);
    }
    #pragma unroll
    for (int i = 0; i < 8; i++) {
        int idx = t + i * 256;
        int k = idx >> 5, c = idx & 31;
        ws2[k][c] = W2[k * 32 + c];
    }
    __syncthreads();
    int c = t & 31, r0 = t >> 5;
    float acc[8] = {};
    for (int k = 0; k < 64; k++) {
        float b = ws2[k][c];
        #pragma unroll
        for (int i = 0; i < 8; i++) acc[i] += es[r0 + 8 * i][k] * b;
    }
    float bv = b2[c];
    #pragma unroll
    for (int i = 0; i < 8; i++) {
        int gr = row0 + r0 + 8 * i;
        if (gr < Nn) {
            float v = acc[i] + bv;
            d_tmp2[gr * 32 + c] = v;
            atomicAdd(&ssum[c], v);
            atomicAdd(&ssq[c], v * v);
        }
    }
    __syncthreads();
    if (t < 32) { atomicAdd(&d_sum2[t], ssum[t]); atomicAdd(&d_ssq2[t], ssq[t]); }
}

// ---------------- h1 = elu(bn(tmp2))@Wg1 -> fp16  (stats2 inline) ----------------
__global__ void __launch_bounds__(256) k_h1(const float* __restrict__ Wg1,
                                            const float* __restrict__ g2,
                                            const float* __restrict__ be2) {
    __shared__ float es[64][33];
    __shared__ float wg[32][33];
    __shared__ float m2s[32], r2s[32];
    int t = threadIdx.x;
    int row0 = blockIdx.x * 64;
    if (t < 32) {
        float m = d_sum2[t] * (1.0f / (float)Nn);
        float v = d_ssq2[t] * (1.0f / (float)Nn) - m * m;
        m2s[t] = m;
        r2s[t] = rsqrtf(v + 1e-3f);
    }
    __syncthreads();
    #pragma unroll
    for (int i = 0; i < 8; i++) {
        int idx = t + i * 256;
        int r = idx >> 5, c = idx & 31;
        int gr = row0 + r;
        float v = (gr < Nn) ? d_tmp2[gr * 32 + c] : 0.f;
        es[r][c] = elu_f(g2[c] * (v - m2s[c]) * r2s[c] + be2[c]);
    }
    #pragma unroll
    for (int i = 0; i < 4; i++) {
        int idx = t + i * 256;
        wg[idx >> 5][idx & 31] = Wg1[idx];
    }
    __syncthreads();
    int c = t & 31, r0 = t >> 5;
    #pragma unroll
    for (int i = 0; i < 8; i++) {
        int r = r0 + 8 * i;
        int gr = row0 + r;
        if (gr >= Nn) continue;
        float acc = 0.f;
        #pragma unroll
        for (int k = 0; k < 32; k++) acc += es[r][k] * wg[k][c];
        d_h1h[gr * 32 + c] = __float2half_rn(acc);
    }
}

// ---------------- conv1: aggregate h1 with both norms, relu, store fp32 + packed half2 ----------------
__global__ void __launch_bounds__(256) k_conv1(const float* __restrict__ bg1) {
    int gw = blockIdx.x * 8 + (threadIdx.x >> 5);
    int lane = threadIdx.x & 31;
    if (gw >= Nn) return;
    int n = gw;
    int beg = d_off[n], end = d_off[n + 1];
    float dp = d_degP[n], dg = d_degG[n];
    float self = __half2float(d_h1h[n * 32 + lane]);
    float bias = bg1[lane];
    float accp = bias + 2.f * dp * dp * self;
    float acca = bias + 2.f * dg * dg * self;
    int j = beg;
    for (; j + 4 <= end; j += 4) {
        int4 e0 = __ldg(&d_sedge[j]);
        int4 e1 = __ldg(&d_sedge[j + 1]);
        int4 e2 = __ldg(&d_sedge[j + 2]);
        int4 e3 = __ldg(&d_sedge[j + 3]);
        float v0 = __half2float(__ldg(&d_h1h[e0.x * 32 + lane]));
        float v1 = __half2float(__ldg(&d_h1h[e1.x * 32 + lane]));
        float v2 = __half2float(__ldg(&d_h1h[e2.x * 32 + lane]));
        float v3 = __half2float(__ldg(&d_h1h[e3.x * 32 + lane]));
        accp += __int_as_float(e0.y) * v0 + __int_as_float(e1.y) * v1
              + __int_as_float(e2.y) * v2 + __int_as_float(e3.y) * v3;
        acca += __int_as_float(e0.z) * v0 + __int_as_float(e1.z) * v1
              + __int_as_float(e2.z) * v2 + __int_as_float(e3.z) * v3;
    }
    for (; j < end; j++) {
        int4 e = __ldg(&d_sedge[j]);
        float v = __half2float(__ldg(&d_h1h[e.x * 32 + lane]));
        accp += __int_as_float(e.y) * v;
        acca += __int_as_float(e.z) * v;
    }
    float fpv = fmaxf(accp, 0.f);
    float fav = fmaxf(acca, 0.f);
    d_fp[n * 32 + lane] = fpv;
    d_fa[n * 32 + lane] = fav;
    __half2 pk = __floats2half2_rn(fpv, fav);
    d_fpfa[n * 32 + lane] = *(uint32_t*)&pk;
}

// ---------------- conv2: aggregate features, project per node, reparam + attention + out ----------------
__global__ void __launch_bounds__(256) k_conv2out(const float* __restrict__ noise_p,
                                                  const float* __restrict__ noise_a,
                                                  const float* __restrict__ Watt,
                                                  const float* __restrict__ batt,
                                                  const float* __restrict__ bg2,
                                                  const float* __restrict__ bg3,
                                                  const float* __restrict__ Wg2,
                                                  const float* __restrict__ Wg3,
                                                  float* __restrict__ out) {
    __shared__ float W2s[32][33], W3s[32][33];
    int t = threadIdx.x;
    for (int i = t; i < 1024; i += 256) {
        int k = i >> 5, c = i & 31;
        W2s[k][c] = Wg2[i];
        W3s[k][c] = Wg3[i];
    }
    __syncthreads();
    int gw = blockIdx.x * 8 + (t >> 5);
    int lane = t & 31;
    if (gw >= Nn) return;
    int n = gw;
    int beg = d_off[n], end = d_off[n + 1];
    float dp = d_degP[n], dg = d_degG[n];
    float fpv = d_fp[n * 32 + lane];   // fp32 self (also used in attention)
    float fav = d_fa[n * 32 + lane];
    // aggregate 32-dim features with both norms (projection commutes with linear agg)
    float aggP = 2.f * dp * dp * fpv;
    float aggA = 2.f * dg * dg * fav;
    int j = beg;
    for (; j + 4 <= end; j += 4) {
        int4 e0 = __ldg(&d_sedge[j]);
        int4 e1 = __ldg(&d_sedge[j + 1]);
        int4 e2 = __ldg(&d_sedge[j + 2]);
        int4 e3 = __ldg(&d_sedge[j + 3]);
        uint32_t g0 = __ldg(&d_fpfa[e0.x * 32 + lane]);
        uint32_t g1 = __ldg(&d_fpfa[e1.x * 32 + lane]);
        uint32_t g2 = __ldg(&d_fpfa[e2.x * 32 + lane]);
        uint32_t g3 = __ldg(&d_fpfa[e3.x * 32 + lane]);
        float2 f0 = __half22float2(*(__half2*)&g0);
        float2 f1 = __half22float2(*(__half2*)&g1);
        float2 f2 = __half22float2(*(__half2*)&g2);
        float2 f3 = __half22float2(*(__half2*)&g3);
        aggP += __int_as_float(e0.y) * f0.x + __int_as_float(e1.y) * f1.x
              + __int_as_float(e2.y) * f2.x + __int_as_float(e3.y) * f3.x;
        aggA += __int_as_float(e0.z) * f0.y + __int_as_float(e1.z) * f1.y
              + __int_as_float(e2.z) * f2.y + __int_as_float(e3.z) * f3.y;
    }
    for (; j < end; j++) {
        int4 e = __ldg(&d_sedge[j]);
        uint32_t g = __ldg(&d_fpfa[e.x * 32 + lane]);
        float2 f = __half22float2(*(__half2*)&g);
        aggP += __int_as_float(e.y) * f.x;
        aggA += __int_as_float(e.z) * f.y;
    }
    // project per node: mu = agg@Wg2 + bg2, lv = agg@Wg3 + bg3 (warp broadcast)
    float mup = bg2[lane], lvp = bg3[lane];
    float mua = mup, lva = lvp;
    #pragma unroll
    for (int k = 0; k < 32; k++) {
        float pk = __shfl_sync(0xffffffffu, aggP, k);
        float ak = __shfl_sync(0xffffffffu, aggA, k);
        float w2 = W2s[k][lane], w3 = W3s[k][lane];
        mup += pk * w2; lvp += pk * w3;
        mua += ak * w2; lva += ak * w3;
    }
    float zp = noise_p[n * 32 + lane] * expf(lvp) + mup;
    float za = noise_a[n * 32 + lane] * expf(lva) + mua;
    float wv = Watt[lane];
    float b0 = batt[0];
    float la = warp_sum(fpv * wv) + b0;
    float lb = warp_sum(fav * wv) + b0;
    float lc = warp_sum(zp * wv) + b0;
    float ld = warp_sum(za * wv) + b0;
    float m1 = fmaxf(la, lb);
    float ea = expf(la - m1), eb = expf(lb - m1);
    float wa = ea / (ea + eb);
    float zf = wa * fpv + (1.f - wa) * fav;
    float m2 = fmaxf(lc, ld);
    float ec = expf(lc - m2), ed = expf(ld - m2);
    float wc = ec / (ec + ed);
    float zg = wc * zp + (1.f - wc) * za;
    out[n * 64 + lane] = zf;
    out[n * 64 + 32 + lane] = zg;
}

// ---------------- launch ----------------
extern "C" void kernel_launch(void* const* d_in, const int* in_sizes, int n_in,
                              void* d_out, int out_size) {
    const float* x       = (const float*)d_in[0];
    const int*   eidx    = (const int*)d_in[1];
    const float* ppmi    = (const float*)d_in[2];
    const float* noise_p = (const float*)d_in[3];
    const float* noise_a = (const float*)d_in[4];
    const float* W1  = (const float*)d_in[5];
    const float* b1  = (const float*)d_in[6];
    const float* g1  = (const float*)d_in[7];
    const float* be1 = (const float*)d_in[8];
    const float* W2  = (const float*)d_in[9];
    const float* b2  = (const float*)d_in[10];
    const float* g2  = (const float*)d_in[11];
    const float* be2 = (const float*)d_in[12];
    const float* Wg1 = (const float*)d_in[13];
    const float* bg1 = (const float*)d_in[14];
    const float* Wg2 = (const float*)d_in[15];
    const float* bg2 = (const float*)d_in[16];
    const float* Wg3 = (const float*)d_in[17];
    const float* bg3 = (const float*)d_in[18];
    const float* Watt = (const float*)d_in[19];
    const float* batt = (const float*)d_in[20];
    float* out = (float*)d_out;

    const int* src = eidx;
    const int* dst = eidx + Ee;

    int nblkN = (Nn + 255) / 256;
    int nscan = (Nn + 1023) / 1024;
    int nwarp = (Nn + 7) / 8;
    int nblk64 = (Nn + 63) / 64;
    int nblk128 = (Nn + 127) / 128;

    k_init<<<nblkN, 256>>>();
    k_deg<<<(Ee + 255) / 256, 256>>>(src, dst, ppmi);
    k_scan1<<<nscan, 1024>>>();
    k_scan2<<<1, 32>>>(nscan);
    k_scan3<<<nblkN, 256>>>();
    k_reorder<<<(Ee + 255) / 256, 256>>>(src, dst, ppmi);
    k_gemm1<<<nblk128, 256>>>(x, W1, b1);
    k_gemm2<<<nblk64, 256>>>(W2, b2, g1, be1);
    k_h1<<<nblk64, 256>>>(Wg1, g2, be2);
    k_conv1<<<nwarp, 256>>>(bg1);
    k_conv2out<<<nwarp, 256>>>(noise_p, noise_a, Watt, batt, bg2, bg3, Wg2, Wg3, out);
}